// round 1
// baseline (speedup 1.0000x reference)
#include <cuda_runtime.h>
#include <cstdint>
#include <climits>
#include <cstdio>

#define Bn 8
#define Cc 240
#define Nn 16384
#define Rr 32
#define Vv 32768           // R^3
#define K2 480             // 2*C

// ---------------- scratch (static device globals; no allocations) ----------------
__device__ float g_sums[(size_t)Bn * Vv * Cc];   // avg accumulators  (~252 MB)
__device__ int   g_maxk[(size_t)Bn * Vv * Cc];   // max keys -> reused as float after finalize
__device__ int   g_cnt [(size_t)Bn * Vv];
__device__ int   g_idx [(size_t)Bn * Nn];
__device__ float g_stats[Bn * 4];                // mean x,y,z + denom per batch

// monotonic float<->int key for atomicMax on signed int
__device__ __forceinline__ int fkey(float f) {
    int i = __float_as_int(f);
    return i ^ ((i >> 31) & 0x7fffffff);
}
__device__ __forceinline__ float fdecode(int k) {
    int i = k ^ ((k >> 31) & 0x7fffffff);
    return __int_as_float(i);
}

// ---------------- 0) re-init scratch each replay ----------------
__global__ void init_kernel() {
    int i = blockIdx.x * blockDim.x + threadIdx.x;           // < 15,728,640
    float4 z = make_float4(0.f, 0.f, 0.f, 0.f);
    reinterpret_cast<float4*>(g_sums)[i] = z;
    int4 m = make_int4(INT_MIN, INT_MIN, INT_MIN, INT_MIN);
    reinterpret_cast<int4*>(g_maxk)[i] = m;
    if (i < (Bn * Vv) / 4)
        reinterpret_cast<int4*>(g_cnt)[i] = make_int4(0, 0, 0, 0);
}

// ---------------- 1) per-batch mean + max norm ----------------
__global__ void stats_kernel(const float* __restrict__ coords) {
    __shared__ float sm[512];
    __shared__ float smean[3];
    int b = blockIdx.x, t = threadIdx.x;
    const float* cx = coords + (size_t)b * 3 * Nn;
    float sx = 0.f, sy = 0.f, sz = 0.f;
    for (int n = t; n < Nn; n += 512) {
        sx += cx[n];
        sy += cx[Nn + n];
        sz += cx[2 * Nn + n];
    }
    float vals[3] = {sx, sy, sz};
    for (int d = 0; d < 3; ++d) {
        sm[t] = vals[d];
        __syncthreads();
        for (int s = 256; s > 0; s >>= 1) {
            if (t < s) sm[t] += sm[t + s];
            __syncthreads();
        }
        if (t == 0) smean[d] = sm[0] / (float)Nn;
        __syncthreads();
    }
    float mx = smean[0], my = smean[1], mz = smean[2];
    float mnorm = 0.f;
    for (int n = t; n < Nn; n += 512) {
        float x = cx[n] - mx, y = cx[Nn + n] - my, z = cx[2 * Nn + n] - mz;
        mnorm = fmaxf(mnorm, sqrtf(x * x + y * y + z * z));
    }
    sm[t] = mnorm;
    __syncthreads();
    for (int s = 256; s > 0; s >>= 1) {
        if (t < s) sm[t] = fmaxf(sm[t], sm[t + s]);
        __syncthreads();
    }
    if (t == 0) {
        g_stats[b * 4 + 0] = mx;
        g_stats[b * 4 + 1] = my;
        g_stats[b * 4 + 2] = mz;
        g_stats[b * 4 + 3] = sm[0] * 2.0f;   // denom (EPS = 0)
    }
}

// ---------------- 2) normalized coords (output) + voxel idx + counts ----------------
__global__ void points_kernel(const float* __restrict__ coords, float* __restrict__ nc_out) {
    int i = blockIdx.x * blockDim.x + threadIdx.x;   // < B*N
    int b = i >> 14;
    int n = i & (Nn - 1);
    float mx = g_stats[b * 4 + 0], my = g_stats[b * 4 + 1];
    float mz = g_stats[b * 4 + 2], dn = g_stats[b * 4 + 3];
    const float* cb = coords + (size_t)b * 3 * Nn;
    float x = cb[n], y = cb[Nn + n], z = cb[2 * Nn + n];

    float ncx = ((x - mx) / dn + 0.5f) * (float)Rr;
    float ncy = ((y - my) / dn + 0.5f) * (float)Rr;
    float ncz = ((z - mz) / dn + 0.5f) * (float)Rr;
    ncx = fminf(fmaxf(ncx, 0.f), (float)(Rr - 1));
    ncy = fminf(fmaxf(ncy, 0.f), (float)(Rr - 1));
    ncz = fminf(fmaxf(ncz, 0.f), (float)(Rr - 1));

    float* nb = nc_out + (size_t)b * 3 * Nn;
    nb[n] = ncx;
    nb[Nn + n] = ncy;
    nb[2 * Nn + n] = ncz;

    int vx = (int)rintf(ncx);   // rintf == round-half-even == jnp.round
    int vy = (int)rintf(ncy);
    int vz = (int)rintf(ncz);
    int idx = vx * (Rr * Rr) + vy * Rr + vz;
    g_idx[i] = idx;
    atomicAdd(&g_cnt[b * Vv + idx], 1);
}

// ---------------- 3) dual scatter (sum + max) ----------------
__global__ void scatter_kernel(const float* __restrict__ features) {
    int b = blockIdx.x >> 6;                 // N/256 = 64 blocks per batch
    int n = ((blockIdx.x & 63) << 8) + threadIdx.x;
    int vidx = g_idx[b * Nn + n];
    size_t base = ((size_t)b * Vv + vidx) * Cc;
    const float* f = features + (size_t)b * Cc * Nn + n;
#pragma unroll 4
    for (int c = 0; c < Cc; ++c) {
        float val = f[(size_t)c * Nn];
        atomicAdd(&g_sums[base + c], val);
        atomicMax(&g_maxk[base + c], fkey(val));
    }
}

// ---------------- 4) finalize: decode max, sums -> avg (in place) ----------------
__global__ void finalize_kernel() {
    int row = blockIdx.x;           // B*V rows
    int c = threadIdx.x;
    if (c >= Cc) return;
    int cnt = g_cnt[row];
    size_t i = (size_t)row * Cc + c;
    float inv = 1.0f / (float)max(cnt, 1);
    reinterpret_cast<float*>(g_maxk)[i] = (cnt > 0) ? fdecode(g_maxk[i]) : 0.0f;
    g_sums[i] *= inv;
}

// ---------------- 5) fused GEMM [M=B*V, N=240, K=480] + bias + BN + Swish ----------------
// BM=128, BN=48, BK=16; 128 threads; per-thread micro-tile 8x6.
// K tiles 0..14 read the max buffer, 15..29 the avg buffer (boundary on a tile edge).
__global__ void __launch_bounds__(128) gemm_kernel(
    const float* __restrict__ W,      // [240][480]
    const float* __restrict__ bias,
    const float* __restrict__ gamma,
    const float* __restrict__ beta,
    const float* __restrict__ bmean,
    const float* __restrict__ bvar,
    float* __restrict__ out)          // [B][240][V]
{
    __shared__ float As[16][128];
    __shared__ float Bs[16][48];

    int tid = threadIdx.x;
    int bx = blockIdx.x;
    int b = bx >> 8;                 // V/128 = 256 blocks per batch
    int v0 = (bx & 255) << 7;
    int n0 = blockIdx.y * 48;

    const float* maxf = reinterpret_cast<const float*>(g_maxk);
    size_t arow = ((size_t)b * Vv + v0) * Cc;

    int ty = tid >> 3, tx = tid & 7;
    int m0 = ty * 8, q0 = tx * 6;

    float acc[8][6];
#pragma unroll
    for (int i = 0; i < 8; ++i)
#pragma unroll
        for (int j = 0; j < 6; ++j) acc[i][j] = 0.f;

    for (int kt = 0; kt < 30; ++kt) {
        const float* Abase = (kt < 15 ? maxf : g_sums) + arow + (size_t)((kt < 15 ? kt : kt - 15) * 16);
        // A tile: each thread loads one 16-float row segment (4x float4)
        {
            const float4* src = reinterpret_cast<const float4*>(Abase + (size_t)tid * Cc);
            float4 a0 = src[0], a1 = src[1], a2 = src[2], a3 = src[3];
            float av[16] = {a0.x, a0.y, a0.z, a0.w, a1.x, a1.y, a1.z, a1.w,
                            a2.x, a2.y, a2.z, a2.w, a3.x, a3.y, a3.z, a3.w};
#pragma unroll
            for (int q = 0; q < 16; ++q) As[q][tid] = av[q];
        }
        // B tile: 48 rows x 16 k = 192 float4 loads
        {
            int kg = kt * 16;
            int nn = tid >> 2;
            int kk4 = (tid & 3) * 4;
            float4 w = *reinterpret_cast<const float4*>(W + (size_t)(n0 + nn) * K2 + kg + kk4);
            Bs[kk4 + 0][nn] = w.x; Bs[kk4 + 1][nn] = w.y;
            Bs[kk4 + 2][nn] = w.z; Bs[kk4 + 3][nn] = w.w;
            if (tid < 64) {
                int i2 = tid + 128;
                nn = i2 >> 2;
                kk4 = (i2 & 3) * 4;
                w = *reinterpret_cast<const float4*>(W + (size_t)(n0 + nn) * K2 + kg + kk4);
                Bs[kk4 + 0][nn] = w.x; Bs[kk4 + 1][nn] = w.y;
                Bs[kk4 + 2][nn] = w.z; Bs[kk4 + 3][nn] = w.w;
            }
        }
        __syncthreads();
#pragma unroll
        for (int kk = 0; kk < 16; ++kk) {
            float4 A0 = *reinterpret_cast<const float4*>(&As[kk][m0]);
            float4 A1 = *reinterpret_cast<const float4*>(&As[kk][m0 + 4]);
            float a[8] = {A0.x, A0.y, A0.z, A0.w, A1.x, A1.y, A1.z, A1.w};
            float bb[6];
#pragma unroll
            for (int j = 0; j < 6; ++j) bb[j] = Bs[kk][q0 + j];
#pragma unroll
            for (int i = 0; i < 8; ++i)
#pragma unroll
                for (int j = 0; j < 6; ++j) acc[i][j] += a[i] * bb[j];
        }
        __syncthreads();
    }

    // epilogue: bias + BN(eval) + swish; out[b][o][v] with v contiguous
    size_t obase = (size_t)b * Cc * Vv + v0 + m0;
#pragma unroll
    for (int j = 0; j < 6; ++j) {
        int o = n0 + q0 + j;
        float s  = gamma[o] * rsqrtf(bvar[o] + 1e-5f);
        float sh = beta[o] - bmean[o] * s;
        float bi = bias[o];
        float r[8];
#pragma unroll
        for (int i = 0; i < 8; ++i) {
            float y = (acc[i][j] + bi) * s + sh;
            r[i] = y / (1.0f + expf(-y));
        }
        float* op = out + obase + (size_t)o * Vv;
        *reinterpret_cast<float4*>(op)     = make_float4(r[0], r[1], r[2], r[3]);
        *reinterpret_cast<float4*>(op + 4) = make_float4(r[4], r[5], r[6], r[7]);
    }
}

// ---------------- launch ----------------
extern "C" void kernel_launch(void* const* d_in, const int* in_sizes, int n_in,
                              void* d_out, int out_size) {
    const float* features = (const float*)d_in[0];
    const float* coords   = (const float*)d_in[1];
    const float* conv_w   = (const float*)d_in[2];
    const float* conv_b   = (const float*)d_in[3];
    const float* bn_gamma = (const float*)d_in[4];
    const float* bn_beta  = (const float*)d_in[5];
    const float* bn_mean  = (const float*)d_in[6];
    const float* bn_var   = (const float*)d_in[7];

    float* out = (float*)d_out;                       // [B, C, R^3]
    float* nc_out = out + (size_t)Bn * Cc * Vv;       // [B, 3, N]

    init_kernel<<<61440, 256>>>();
    stats_kernel<<<Bn, 512>>>(coords);
    points_kernel<<<(Bn * Nn) / 256, 256>>>(coords, nc_out);
    scatter_kernel<<<(Bn * Nn) / 256, 256>>>(features);
    finalize_kernel<<<Bn * Vv, 256>>>();
    gemm_kernel<<<dim3((Bn * Vv) / 128, 5), 128>>>(conv_w, conv_b, bn_gamma, bn_beta,
                                                   bn_mean, bn_var, out);
}

// round 2
// speedup vs baseline: 4.8076x; 4.8076x over previous
#include <cuda_runtime.h>
#include <cstdint>
#include <climits>
#include <cmath>

#define Bn 8
#define Cc 240
#define Nn 16384
#define Rr 32
#define Vv 32768              // R^3
#define K2 480                // 2*C
#define MAXROWS (Bn * Nn)     // worst case: every point its own voxel (131072)

// ---------------- scratch (static device globals; no allocations) ----------------
__device__ float g_featT[(size_t)Bn * Nn * Cc];   // [B*N][240] transposed features (126 MB)
__device__ float g_A[(size_t)MAXROWS * K2];       // compact GEMM A: [row][max(240)|avg(240)]
__device__ int   g_cnt[Bn * Vv];
__device__ int   g_idx[Bn * Nn];
__device__ int   g_vox2row[Bn * Vv];
__device__ int   g_row2vox[MAXROWS];
__device__ int   g_rowoff[MAXROWS];
__device__ int   g_rowcnt[MAXROWS];
__device__ int   g_fill[MAXROWS];
__device__ int   g_plist[Bn * Nn];
__device__ int   g_nrows;
__device__ int   g_cursor;
__device__ float g_stats[Bn * 4];
__device__ float g_empty[Cc];

// ---------------- 0) zero counters each replay ----------------
__global__ void zero_kernel() {
    int i = blockIdx.x * blockDim.x + threadIdx.x;   // < B*V
    g_cnt[i] = 0;
    if (i == 0) { g_nrows = 0; g_cursor = 0; }
}

// ---------------- 1) per-batch mean + max norm ----------------
__global__ void stats_kernel(const float* __restrict__ coords) {
    __shared__ float sm[512];
    __shared__ float smean[3];
    int b = blockIdx.x, t = threadIdx.x;
    const float* cx = coords + (size_t)b * 3 * Nn;
    float sx = 0.f, sy = 0.f, sz = 0.f;
    for (int n = t; n < Nn; n += 512) {
        sx += cx[n];
        sy += cx[Nn + n];
        sz += cx[2 * Nn + n];
    }
    float vals[3] = {sx, sy, sz};
    for (int d = 0; d < 3; ++d) {
        sm[t] = vals[d];
        __syncthreads();
        for (int s = 256; s > 0; s >>= 1) {
            if (t < s) sm[t] += sm[t + s];
            __syncthreads();
        }
        if (t == 0) smean[d] = sm[0] / (float)Nn;
        __syncthreads();
    }
    float mx = smean[0], my = smean[1], mz = smean[2];
    float mnorm = 0.f;
    for (int n = t; n < Nn; n += 512) {
        float x = cx[n] - mx, y = cx[Nn + n] - my, z = cx[2 * Nn + n] - mz;
        mnorm = fmaxf(mnorm, sqrtf(x * x + y * y + z * z));
    }
    sm[t] = mnorm;
    __syncthreads();
    for (int s = 256; s > 0; s >>= 1) {
        if (t < s) sm[t] = fmaxf(sm[t], sm[t + s]);
        __syncthreads();
    }
    if (t == 0) {
        g_stats[b * 4 + 0] = mx;
        g_stats[b * 4 + 1] = my;
        g_stats[b * 4 + 2] = mz;
        g_stats[b * 4 + 3] = sm[0] * 2.0f;   // denom (EPS = 0)
    }
}

// ---------------- 2) normalized coords (output) + voxel idx + counts ----------------
__global__ void points_kernel(const float* __restrict__ coords, float* __restrict__ nc_out) {
    int i = blockIdx.x * blockDim.x + threadIdx.x;   // < B*N
    int b = i >> 14;
    int n = i & (Nn - 1);
    float mx = g_stats[b * 4 + 0], my = g_stats[b * 4 + 1];
    float mz = g_stats[b * 4 + 2], dn = g_stats[b * 4 + 3];
    const float* cb = coords + (size_t)b * 3 * Nn;
    float x = cb[n], y = cb[Nn + n], z = cb[2 * Nn + n];

    float ncx = ((x - mx) / dn + 0.5f) * (float)Rr;
    float ncy = ((y - my) / dn + 0.5f) * (float)Rr;
    float ncz = ((z - mz) / dn + 0.5f) * (float)Rr;
    ncx = fminf(fmaxf(ncx, 0.f), (float)(Rr - 1));
    ncy = fminf(fmaxf(ncy, 0.f), (float)(Rr - 1));
    ncz = fminf(fmaxf(ncz, 0.f), (float)(Rr - 1));

    float* nb = nc_out + (size_t)b * 3 * Nn;
    nb[n] = ncx;
    nb[Nn + n] = ncy;
    nb[2 * Nn + n] = ncz;

    int vx = (int)rintf(ncx);   // round-half-even == jnp.round
    int vy = (int)rintf(ncy);
    int vz = (int)rintf(ncz);
    int idx = vx * (Rr * Rr) + vy * Rr + vz;
    g_idx[i] = idx;
    atomicAdd(&g_cnt[b * Vv + idx], 1);
}

// ---------------- 3) transpose features [B][C][N] -> [B*N][C] ----------------
__global__ void transpose_kernel(const float* __restrict__ f) {
    __shared__ float t[32][33];
    int b = blockIdx.z;
    int n0 = blockIdx.x * 32, c0 = blockIdx.y * 32;
    for (int i = threadIdx.y; i < 32; i += 8) {
        int c = c0 + i;
        if (c < Cc)
            t[i][threadIdx.x] = f[((size_t)b * Cc + c) * Nn + n0 + threadIdx.x];
    }
    __syncthreads();
    for (int i = threadIdx.y; i < 32; i += 8) {
        int c = c0 + threadIdx.x;
        if (c < Cc)
            g_featT[((size_t)b * Nn + n0 + i) * Cc + c] = t[threadIdx.x][i];
    }
}

// ---------------- 4) compact occupied voxels ----------------
__global__ void compact_kernel() {
    int bv = blockIdx.x * blockDim.x + threadIdx.x;   // < B*V
    int cnt = g_cnt[bv];
    if (cnt > 0) {
        int row = atomicAdd(&g_nrows, 1);
        int off = atomicAdd(&g_cursor, cnt);
        g_vox2row[bv] = row;
        g_row2vox[row] = bv;
        g_rowcnt[row] = cnt;
        g_rowoff[row] = off;
        g_fill[row] = 0;
    }
}

// ---------------- 5) fill CSR point lists ----------------
__global__ void fill_lists_kernel() {
    int i = blockIdx.x * blockDim.x + threadIdx.x;    // < B*N
    int b = i >> 14;
    int bv = b * Vv + g_idx[i];
    int row = g_vox2row[bv];
    int slot = atomicAdd(&g_fill[row], 1);
    g_plist[g_rowoff[row] + slot] = i;                // index into g_featT rows
}

// ---------------- 6) gather reduce: per occupied voxel, max + avg ----------------
__global__ void reduce_kernel() {
    int row = blockIdx.x;
    if (row >= g_nrows) return;
    int c = threadIdx.x;
    if (c >= Cc) return;
    int cnt = g_rowcnt[row];
    int off = g_rowoff[row];
    float s = 0.f, m = -INFINITY;
    for (int p = 0; p < cnt; ++p) {
        int pi = g_plist[off + p];
        float v = g_featT[(size_t)pi * Cc + c];
        s += v;
        m = fmaxf(m, v);
    }
    g_A[(size_t)row * K2 + c] = m;                    // concat: [max | avg]
    g_A[(size_t)row * K2 + Cc + c] = s / (float)cnt;
}

// ---------------- 7) per-channel empty-voxel constant ----------------
__global__ void empty_kernel(const float* __restrict__ bias,
                             const float* __restrict__ gamma,
                             const float* __restrict__ beta,
                             const float* __restrict__ bmean,
                             const float* __restrict__ bvar) {
    int o = threadIdx.x;
    float s = gamma[o] * rsqrtf(bvar[o] + 1e-5f);
    float y = (bias[o] - bmean[o]) * s + beta[o];
    g_empty[o] = y / (1.0f + expf(-y));
}

// ---------------- 8) fill output with empty constants ----------------
__global__ void fill_out_kernel(float* __restrict__ out) {
    int i = blockIdx.x * blockDim.x + threadIdx.x;    // float4 index < B*C*V/4
    int o = (i >> 13) % Cc;                           // V/4 = 8192 float4 per channel
    float e = g_empty[o];
    reinterpret_cast<float4*>(out)[i] = make_float4(e, e, e, e);
}

// ---------------- 9) GEMM over occupied rows [M=nrows, N=240, K=480] + epilogue ----------------
// BM=128, BN=48, BK=16; 128 threads; 8x6 micro-tile. Scattered store to out[b][o][v].
__global__ void __launch_bounds__(128) gemm_kernel(
    const float* __restrict__ W,      // [240][480]
    const float* __restrict__ bias,
    const float* __restrict__ gamma,
    const float* __restrict__ beta,
    const float* __restrict__ bmean,
    const float* __restrict__ bvar,
    float* __restrict__ out)          // [B][240][V]
{
    int nrows = g_nrows;
    int row0 = blockIdx.x << 7;
    if (row0 >= nrows) return;

    __shared__ float As[16][128];
    __shared__ float Bs[16][48];

    int tid = threadIdx.x;
    int n0 = blockIdx.y * 48;
    int ty = tid >> 3, tx = tid & 7;
    int m0 = ty * 8, q0 = tx * 6;

    float acc[8][6];
#pragma unroll
    for (int i = 0; i < 8; ++i)
#pragma unroll
        for (int j = 0; j < 6; ++j) acc[i][j] = 0.f;

    for (int kt = 0; kt < 30; ++kt) {
        {   // A tile: thread = one row, 16 k-floats (4x float4). In-bounds even past nrows.
            const float4* src = reinterpret_cast<const float4*>(
                g_A + (size_t)(row0 + tid) * K2 + kt * 16);
            float4 a0 = src[0], a1 = src[1], a2 = src[2], a3 = src[3];
            float av[16] = {a0.x, a0.y, a0.z, a0.w, a1.x, a1.y, a1.z, a1.w,
                            a2.x, a2.y, a2.z, a2.w, a3.x, a3.y, a3.z, a3.w};
#pragma unroll
            for (int q = 0; q < 16; ++q) As[q][tid] = av[q];
        }
        {   // B tile: 48 rows x 16 k
            int kg = kt * 16;
            int nn = tid >> 2;
            int kk4 = (tid & 3) * 4;
            float4 w = *reinterpret_cast<const float4*>(W + (size_t)(n0 + nn) * K2 + kg + kk4);
            Bs[kk4 + 0][nn] = w.x; Bs[kk4 + 1][nn] = w.y;
            Bs[kk4 + 2][nn] = w.z; Bs[kk4 + 3][nn] = w.w;
            if (tid < 64) {
                int i2 = tid + 128;
                nn = i2 >> 2;
                kk4 = (i2 & 3) * 4;
                w = *reinterpret_cast<const float4*>(W + (size_t)(n0 + nn) * K2 + kg + kk4);
                Bs[kk4 + 0][nn] = w.x; Bs[kk4 + 1][nn] = w.y;
                Bs[kk4 + 2][nn] = w.z; Bs[kk4 + 3][nn] = w.w;
            }
        }
        __syncthreads();
#pragma unroll
        for (int kk = 0; kk < 16; ++kk) {
            float4 A0 = *reinterpret_cast<const float4*>(&As[kk][m0]);
            float4 A1 = *reinterpret_cast<const float4*>(&As[kk][m0 + 4]);
            float a[8] = {A0.x, A0.y, A0.z, A0.w, A1.x, A1.y, A1.z, A1.w};
            float bb[6];
#pragma unroll
            for (int j = 0; j < 6; ++j) bb[j] = Bs[kk][q0 + j];
#pragma unroll
            for (int i = 0; i < 8; ++i)
#pragma unroll
                for (int j = 0; j < 6; ++j) acc[i][j] += a[i] * bb[j];
        }
        __syncthreads();
    }

    // epilogue: bias + BN(eval) + swish, scatter to out[b][o][v]
    int bvr[8];
#pragma unroll
    for (int i = 0; i < 8; ++i) {
        int row = row0 + m0 + i;
        bvr[i] = (row < nrows) ? g_row2vox[row] : -1;
    }
#pragma unroll
    for (int j = 0; j < 6; ++j) {
        int o = n0 + q0 + j;
        float s  = gamma[o] * rsqrtf(bvar[o] + 1e-5f);
        float sh = beta[o] - bmean[o] * s;
        float bi = bias[o];
#pragma unroll
        for (int i = 0; i < 8; ++i) {
            if (bvr[i] >= 0) {
                float y = (acc[i][j] + bi) * s + sh;
                y = y / (1.0f + expf(-y));
                int b = bvr[i] >> 15;
                int v = bvr[i] & (Vv - 1);
                out[((size_t)b * Cc + o) * Vv + v] = y;
            }
        }
    }
}

// ---------------- launch ----------------
extern "C" void kernel_launch(void* const* d_in, const int* in_sizes, int n_in,
                              void* d_out, int out_size) {
    const float* features = (const float*)d_in[0];
    const float* coords   = (const float*)d_in[1];
    const float* conv_w   = (const float*)d_in[2];
    const float* conv_b   = (const float*)d_in[3];
    const float* bn_gamma = (const float*)d_in[4];
    const float* bn_beta  = (const float*)d_in[5];
    const float* bn_mean  = (const float*)d_in[6];
    const float* bn_var   = (const float*)d_in[7];

    float* out = (float*)d_out;                       // [B, C, R^3]
    float* nc_out = out + (size_t)Bn * Cc * Vv;       // [B, 3, N]

    zero_kernel<<<(Bn * Vv) / 256, 256>>>();
    stats_kernel<<<Bn, 512>>>(coords);
    points_kernel<<<(Bn * Nn) / 256, 256>>>(coords, nc_out);
    transpose_kernel<<<dim3(Nn / 32, 8, Bn), dim3(32, 8)>>>(features);
    compact_kernel<<<(Bn * Vv) / 256, 256>>>();
    fill_lists_kernel<<<(Bn * Nn) / 256, 256>>>();
    reduce_kernel<<<MAXROWS, 256>>>();
    empty_kernel<<<1, Cc>>>(conv_b, bn_gamma, bn_beta, bn_mean, bn_var);
    fill_out_kernel<<<(Bn * Cc * Vv) / 4 / 256, 256>>>(out);
    gemm_kernel<<<dim3(MAXROWS / 128, 5), 128>>>(conv_w, conv_b, bn_gamma, bn_beta,
                                                 bn_mean, bn_var, out);
}

// round 3
// speedup vs baseline: 6.1758x; 1.2846x over previous
#include <cuda_runtime.h>
#include <cstdint>
#include <climits>
#include <cmath>

#define Bn 8
#define Cc 240
#define Nn 16384
#define Rr 32
#define Vv 32768              // R^3
#define K2 480                // 2*C
#define FS 256                // padded row stride of g_featT
#define MAXROWS (Bn * Nn)     // worst case: every point its own voxel (131072)

// ---------------- scratch (static device globals; no allocations) ----------------
__device__ float g_featT[(size_t)Bn * Nn * FS];   // [B*N][256] padded transposed features
__device__ float g_A[(size_t)MAXROWS * K2];       // compact GEMM A: [row][max(240)|avg(240)]
__device__ int   g_cnt[Bn * Vv];
__device__ int   g_idx[Bn * Nn];
__device__ int   g_vox2row[Bn * Vv];
__device__ int   g_row2vox[MAXROWS];
__device__ int   g_rowoff[MAXROWS];
__device__ int   g_rowcnt[MAXROWS];
__device__ int   g_fill[MAXROWS];
__device__ int   g_plist[Bn * Nn];
__device__ int   g_nrows;
__device__ int   g_cursor;
__device__ float g_stats[Bn * 4];
__device__ float g_empty[Cc];

__device__ __forceinline__ float tf32r(float x) {
    uint32_t u;
    asm("cvt.rna.tf32.f32 %0, %1;" : "=r"(u) : "f"(x));
    return __uint_as_float(u);
}

__device__ __forceinline__ void mma_tf32(float* c, const uint32_t* a, const uint32_t* b) {
    asm volatile(
        "mma.sync.aligned.m16n8k8.row.col.f32.tf32.tf32.f32 "
        "{%0,%1,%2,%3}, {%4,%5,%6,%7}, {%8,%9}, {%0,%1,%2,%3};"
        : "+f"(c[0]), "+f"(c[1]), "+f"(c[2]), "+f"(c[3])
        : "r"(a[0]), "r"(a[1]), "r"(a[2]), "r"(a[3]), "r"(b[0]), "r"(b[1]));
}

// ---------------- 0) zero counters each replay ----------------
__global__ void zero_kernel() {
    int i = blockIdx.x * blockDim.x + threadIdx.x;   // < B*V
    g_cnt[i] = 0;
    if (i == 0) { g_nrows = 0; g_cursor = 0; }
}

// ---------------- 1) per-batch mean + max norm ----------------
__global__ void stats_kernel(const float* __restrict__ coords) {
    __shared__ float sm[512];
    __shared__ float smean[3];
    int b = blockIdx.x, t = threadIdx.x;
    const float* cx = coords + (size_t)b * 3 * Nn;
    float sx = 0.f, sy = 0.f, sz = 0.f;
    for (int n = t; n < Nn; n += 512) {
        sx += cx[n];
        sy += cx[Nn + n];
        sz += cx[2 * Nn + n];
    }
    float vals[3] = {sx, sy, sz};
    for (int d = 0; d < 3; ++d) {
        sm[t] = vals[d];
        __syncthreads();
        for (int s = 256; s > 0; s >>= 1) {
            if (t < s) sm[t] += sm[t + s];
            __syncthreads();
        }
        if (t == 0) smean[d] = sm[0] / (float)Nn;
        __syncthreads();
    }
    float mx = smean[0], my = smean[1], mz = smean[2];
    float mnorm = 0.f;
    for (int n = t; n < Nn; n += 512) {
        float x = cx[n] - mx, y = cx[Nn + n] - my, z = cx[2 * Nn + n] - mz;
        mnorm = fmaxf(mnorm, sqrtf(x * x + y * y + z * z));
    }
    sm[t] = mnorm;
    __syncthreads();
    for (int s = 256; s > 0; s >>= 1) {
        if (t < s) sm[t] = fmaxf(sm[t], sm[t + s]);
        __syncthreads();
    }
    if (t == 0) {
        g_stats[b * 4 + 0] = mx;
        g_stats[b * 4 + 1] = my;
        g_stats[b * 4 + 2] = mz;
        g_stats[b * 4 + 3] = sm[0] * 2.0f;   // denom (EPS = 0)
    }
}

// ---------------- 2) normalized coords (output) + voxel idx + counts ----------------
__global__ void points_kernel(const float* __restrict__ coords, float* __restrict__ nc_out) {
    int i = blockIdx.x * blockDim.x + threadIdx.x;   // < B*N
    int b = i >> 14;
    int n = i & (Nn - 1);
    float mx = g_stats[b * 4 + 0], my = g_stats[b * 4 + 1];
    float mz = g_stats[b * 4 + 2], dn = g_stats[b * 4 + 3];
    const float* cb = coords + (size_t)b * 3 * Nn;
    float x = cb[n], y = cb[Nn + n], z = cb[2 * Nn + n];

    float ncx = ((x - mx) / dn + 0.5f) * (float)Rr;
    float ncy = ((y - my) / dn + 0.5f) * (float)Rr;
    float ncz = ((z - mz) / dn + 0.5f) * (float)Rr;
    ncx = fminf(fmaxf(ncx, 0.f), (float)(Rr - 1));
    ncy = fminf(fmaxf(ncy, 0.f), (float)(Rr - 1));
    ncz = fminf(fmaxf(ncz, 0.f), (float)(Rr - 1));

    float* nb = nc_out + (size_t)b * 3 * Nn;
    nb[n] = ncx;
    nb[Nn + n] = ncy;
    nb[2 * Nn + n] = ncz;

    int vx = (int)rintf(ncx);   // round-half-even == jnp.round
    int vy = (int)rintf(ncy);
    int vz = (int)rintf(ncz);
    int idx = vx * (Rr * Rr) + vy * Rr + vz;
    g_idx[i] = idx;
    atomicAdd(&g_cnt[b * Vv + idx], 1);
}

// ---------------- 3) transpose features [B][C][N] -> [B*N][FS] ----------------
__global__ void transpose_kernel(const float* __restrict__ f) {
    __shared__ float t[32][33];
    int b = blockIdx.z;
    int n0 = blockIdx.x * 32, c0 = blockIdx.y * 32;
    for (int i = threadIdx.y; i < 32; i += 8) {
        int c = c0 + i;
        if (c < Cc)
            t[i][threadIdx.x] = f[((size_t)b * Cc + c) * Nn + n0 + threadIdx.x];
    }
    __syncthreads();
    for (int i = threadIdx.y; i < 32; i += 8) {
        int c = c0 + threadIdx.x;
        if (c < Cc)
            g_featT[((size_t)b * Nn + n0 + i) * FS + c] = t[threadIdx.x][i];
    }
}

// ---------------- 4) compact occupied voxels ----------------
__global__ void compact_kernel() {
    int bv = blockIdx.x * blockDim.x + threadIdx.x;   // < B*V
    int cnt = g_cnt[bv];
    if (cnt > 0) {
        int row = atomicAdd(&g_nrows, 1);
        int off = atomicAdd(&g_cursor, cnt);
        g_vox2row[bv] = row;
        g_row2vox[row] = bv;
        g_rowcnt[row] = cnt;
        g_rowoff[row] = off;
        g_fill[row] = 0;
    }
}

// ---------------- 5) fill CSR point lists ----------------
__global__ void fill_lists_kernel() {
    int i = blockIdx.x * blockDim.x + threadIdx.x;    // < B*N
    int b = i >> 14;
    int bv = b * Vv + g_idx[i];
    int row = g_vox2row[bv];
    int slot = atomicAdd(&g_fill[row], 1);
    g_plist[g_rowoff[row] + slot] = i;                // index into g_featT rows
}

// ---------------- 6) gather reduce: per occupied voxel, max + avg ----------------
__global__ void reduce_kernel() {
    int row = blockIdx.x;
    if (row >= g_nrows) return;
    int c = threadIdx.x;
    if (c >= Cc) return;
    int cnt = g_rowcnt[row];
    int off = g_rowoff[row];
    float s = 0.f, m = -INFINITY;
    for (int p = 0; p < cnt; ++p) {
        int pi = g_plist[off + p];
        float v = g_featT[(size_t)pi * FS + c];
        s += v;
        m = fmaxf(m, v);
    }
    g_A[(size_t)row * K2 + c] = m;                    // concat: [max | avg]
    g_A[(size_t)row * K2 + Cc + c] = s / (float)cnt;
}

// ---------------- 7) per-channel empty-voxel constant ----------------
__global__ void empty_kernel(const float* __restrict__ bias,
                             const float* __restrict__ gamma,
                             const float* __restrict__ beta,
                             const float* __restrict__ bmean,
                             const float* __restrict__ bvar) {
    int o = threadIdx.x;
    float s = gamma[o] * rsqrtf(bvar[o] + 1e-5f);
    float y = (bias[o] - bmean[o]) * s + beta[o];
    g_empty[o] = y / (1.0f + expf(-y));
}

// ---------------- 8) fill output with empty constants ----------------
__global__ void fill_out_kernel(float* __restrict__ out) {
    int i = blockIdx.x * blockDim.x + threadIdx.x;    // float4 index < B*C*V/4
    int o = (i >> 13) % Cc;                           // V/4 = 8192 float4 per channel
    float e = g_empty[o];
    reinterpret_cast<float4*>(out)[i] = make_float4(e, e, e, e);
}

// ---------------- 9) tf32 tensor-core GEMM [M=nrows, N=240, K=480] + epilogue ----------------
// BM=128, BN=48, BK=32; 256 threads = 8 warps (4 M x 2 N); warp tile 32x24 (2x3 m16n8k8).
__global__ void __launch_bounds__(256) gemm_kernel(
    const float* __restrict__ W,      // [240][480]
    const float* __restrict__ bias,
    const float* __restrict__ gamma,
    const float* __restrict__ beta,
    const float* __restrict__ bmean,
    const float* __restrict__ bvar,
    float* __restrict__ out)          // [B][240][V]
{
    int nrows = g_nrows;
    int row0 = blockIdx.x << 7;
    if (row0 >= nrows) return;

    __shared__ float As[128][36];     // stride 36: conflict-free frag loads
    __shared__ float Bs[48][36];
    __shared__ float sc_s[48], sc_o[48];

    int tid = threadIdx.x;
    int n0 = blockIdx.y * 48;

    if (tid < 48) {
        int o = n0 + tid;
        float s = gamma[o] * rsqrtf(bvar[o] + 1e-5f);
        sc_s[tid] = s;
        sc_o[tid] = (bias[o] - bmean[o]) * s + beta[o];
    }

    int lane = tid & 31, warp = tid >> 5;
    int wm = warp & 3, wn = warp >> 2;        // warp M/N position
    int grp = lane >> 2, qk = lane & 3;

    float acc[2][3][4];
#pragma unroll
    for (int mt = 0; mt < 2; ++mt)
#pragma unroll
        for (int nt = 0; nt < 3; ++nt)
#pragma unroll
            for (int q = 0; q < 4; ++q) acc[mt][nt][q] = 0.f;

    int am = tid >> 1, ah = (tid & 1) * 16;   // A loader: row am, k-offset ah
    int bn2 = tid >> 1, bh = (tid & 1) * 16;  // B loader (tid < 96)

    for (int kt = 0; kt < 15; ++kt) {
        int kg = kt * 32;
        {   // A tile: 128 rows x 32 k
            const float4* ap = reinterpret_cast<const float4*>(
                g_A + (size_t)(row0 + am) * K2 + kg + ah);
            float4 v0 = ap[0], v1 = ap[1], v2 = ap[2], v3 = ap[3];
            float av[16] = {v0.x, v0.y, v0.z, v0.w, v1.x, v1.y, v1.z, v1.w,
                            v2.x, v2.y, v2.z, v2.w, v3.x, v3.y, v3.z, v3.w};
#pragma unroll
            for (int i = 0; i < 16; ++i) As[am][ah + i] = tf32r(av[i]);
        }
        if (tid < 96) {   // B tile: 48 rows x 32 k
            const float4* bp = reinterpret_cast<const float4*>(
                W + (size_t)(n0 + bn2) * K2 + kg + bh);
            float4 v0 = bp[0], v1 = bp[1], v2 = bp[2], v3 = bp[3];
            float bv[16] = {v0.x, v0.y, v0.z, v0.w, v1.x, v1.y, v1.z, v1.w,
                            v2.x, v2.y, v2.z, v2.w, v3.x, v3.y, v3.z, v3.w};
#pragma unroll
            for (int i = 0; i < 16; ++i) Bs[bn2][bh + i] = tf32r(bv[i]);
        }
        __syncthreads();

#pragma unroll
        for (int ks = 0; ks < 4; ++ks) {
            int k8 = ks * 8;
            uint32_t a[2][4], b[3][2];
#pragma unroll
            for (int mt = 0; mt < 2; ++mt) {
                int r = wm * 32 + mt * 16 + grp;
                a[mt][0] = __float_as_uint(As[r][k8 + qk]);
                a[mt][1] = __float_as_uint(As[r + 8][k8 + qk]);
                a[mt][2] = __float_as_uint(As[r][k8 + qk + 4]);
                a[mt][3] = __float_as_uint(As[r + 8][k8 + qk + 4]);
            }
#pragma unroll
            for (int nt = 0; nt < 3; ++nt) {
                int nc = wn * 24 + nt * 8 + grp;
                b[nt][0] = __float_as_uint(Bs[nc][k8 + qk]);
                b[nt][1] = __float_as_uint(Bs[nc][k8 + qk + 4]);
            }
#pragma unroll
            for (int mt = 0; mt < 2; ++mt)
#pragma unroll
                for (int nt = 0; nt < 3; ++nt)
                    mma_tf32(acc[mt][nt], a[mt], b[nt]);
        }
        __syncthreads();
    }

    // epilogue: y = acc*s + off, swish, scatter to out[b][o][v]
#pragma unroll
    for (int mt = 0; mt < 2; ++mt) {
        int r0 = row0 + wm * 32 + mt * 16 + grp;
        int r1 = r0 + 8;
        int bv0 = (r0 < nrows) ? g_row2vox[r0] : -1;
        int bv1 = (r1 < nrows) ? g_row2vox[r1] : -1;
        size_t ob0 = 0, ob1 = 0;
        if (bv0 >= 0) ob0 = (size_t)(bv0 >> 15) * Cc * Vv + (bv0 & (Vv - 1));
        if (bv1 >= 0) ob1 = (size_t)(bv1 >> 15) * Cc * Vv + (bv1 & (Vv - 1));
#pragma unroll
        for (int nt = 0; nt < 3; ++nt) {
            int ocl = wn * 24 + nt * 8 + 2 * qk;
#pragma unroll
            for (int h = 0; h < 2; ++h) {
                int ol = ocl + h;
                float s = sc_s[ol], off = sc_o[ol];
                int o = n0 + ol;
                if (bv0 >= 0) {
                    float y = acc[mt][nt][h] * s + off;       // c0/c1 -> row r0
                    y = y / (1.0f + expf(-y));
                    out[ob0 + (size_t)o * Vv] = y;
                }
                if (bv1 >= 0) {
                    float y = acc[mt][nt][2 + h] * s + off;   // c2/c3 -> row r1
                    y = y / (1.0f + expf(-y));
                    out[ob1 + (size_t)o * Vv] = y;
                }
            }
        }
    }
}

// ---------------- launch ----------------
extern "C" void kernel_launch(void* const* d_in, const int* in_sizes, int n_in,
                              void* d_out, int out_size) {
    const float* features = (const float*)d_in[0];
    const float* coords   = (const float*)d_in[1];
    const float* conv_w   = (const float*)d_in[2];
    const float* conv_b   = (const float*)d_in[3];
    const float* bn_gamma = (const float*)d_in[4];
    const float* bn_beta  = (const float*)d_in[5];
    const float* bn_mean  = (const float*)d_in[6];
    const float* bn_var   = (const float*)d_in[7];

    float* out = (float*)d_out;                       // [B, C, R^3]
    float* nc_out = out + (size_t)Bn * Cc * Vv;       // [B, 3, N]

    zero_kernel<<<(Bn * Vv) / 256, 256>>>();
    stats_kernel<<<Bn, 512>>>(coords);
    points_kernel<<<(Bn * Nn) / 256, 256>>>(coords, nc_out);
    transpose_kernel<<<dim3(Nn / 32, 8, Bn), dim3(32, 8)>>>(features);
    compact_kernel<<<(Bn * Vv) / 256, 256>>>();
    fill_lists_kernel<<<(Bn * Nn) / 256, 256>>>();
    reduce_kernel<<<MAXROWS, 256>>>();
    empty_kernel<<<1, Cc>>>(conv_b, bn_gamma, bn_beta, bn_mean, bn_var);
    fill_out_kernel<<<(Bn * Cc * Vv) / 4 / 256, 256>>>(out);
    gemm_kernel<<<dim3(MAXROWS / 128, 5), 256>>>(conv_w, conv_b, bn_gamma, bn_beta,
                                                 bn_mean, bn_var, out);
}

// round 4
// speedup vs baseline: 7.0682x; 1.1445x over previous
#include <cuda_runtime.h>
#include <cstdint>
#include <climits>
#include <cmath>

#define Bn 8
#define Cc 240
#define Nn 16384
#define Rr 32
#define Vv 32768              // R^3
#define K2 480                // 2*C
#define FS 256                // padded row stride of g_featT
#define MAXROWS (Bn * Nn)     // worst case: every point its own voxel (131072)

// ---------------- scratch (static device globals; no allocations) ----------------
__device__ float g_featT[(size_t)Bn * Nn * FS];   // CSR-ordered point features [slot][256]
__device__ float g_A[(size_t)MAXROWS * K2];       // compact GEMM A: [row][max(240)|avg(240)]
__device__ int   g_cnt[Bn * Vv];
__device__ int   g_idx[Bn * Nn];
__device__ int   g_vox2row[Bn * Vv];
__device__ int   g_row2vox[MAXROWS];
__device__ int   g_rowoff[MAXROWS];
__device__ int   g_rowcnt[MAXROWS];
__device__ int   g_fill[MAXROWS];
__device__ int   g_slot[Bn * Nn];                 // CSR destination slot per point
__device__ int   g_nrows;
__device__ int   g_cursor;
__device__ float g_stats[Bn * 4];
__device__ float g_empty[Cc];

__device__ __forceinline__ float tf32r(float x) {
    uint32_t u;
    asm("cvt.rna.tf32.f32 %0, %1;" : "=r"(u) : "f"(x));
    return __uint_as_float(u);
}

__device__ __forceinline__ void mma_tf32(float* c, const uint32_t* a, const uint32_t* b) {
    asm volatile(
        "mma.sync.aligned.m16n8k8.row.col.f32.tf32.tf32.f32 "
        "{%0,%1,%2,%3}, {%4,%5,%6,%7}, {%8,%9}, {%0,%1,%2,%3};"
        : "+f"(c[0]), "+f"(c[1]), "+f"(c[2]), "+f"(c[3])
        : "r"(a[0]), "r"(a[1]), "r"(a[2]), "r"(a[3]), "r"(b[0]), "r"(b[1]));
}

// ---------------- 0) zero counters each replay ----------------
__global__ void zero_kernel() {
    int i = blockIdx.x * blockDim.x + threadIdx.x;   // < B*V
    g_cnt[i] = 0;
    if (i == 0) { g_nrows = 0; g_cursor = 0; }
}

// ---------------- 1) per-batch mean + max norm ----------------
__global__ void stats_kernel(const float* __restrict__ coords) {
    __shared__ float sm[512];
    __shared__ float smean[3];
    int b = blockIdx.x, t = threadIdx.x;
    const float* cx = coords + (size_t)b * 3 * Nn;
    float sx = 0.f, sy = 0.f, sz = 0.f;
    for (int n = t; n < Nn; n += 512) {
        sx += cx[n];
        sy += cx[Nn + n];
        sz += cx[2 * Nn + n];
    }
    float vals[3] = {sx, sy, sz};
    for (int d = 0; d < 3; ++d) {
        sm[t] = vals[d];
        __syncthreads();
        for (int s = 256; s > 0; s >>= 1) {
            if (t < s) sm[t] += sm[t + s];
            __syncthreads();
        }
        if (t == 0) smean[d] = sm[0] / (float)Nn;
        __syncthreads();
    }
    float mx = smean[0], my = smean[1], mz = smean[2];
    float mnorm = 0.f;
    for (int n = t; n < Nn; n += 512) {
        float x = cx[n] - mx, y = cx[Nn + n] - my, z = cx[2 * Nn + n] - mz;
        mnorm = fmaxf(mnorm, sqrtf(x * x + y * y + z * z));
    }
    sm[t] = mnorm;
    __syncthreads();
    for (int s = 256; s > 0; s >>= 1) {
        if (t < s) sm[t] = fmaxf(sm[t], sm[t + s]);
        __syncthreads();
    }
    if (t == 0) {
        g_stats[b * 4 + 0] = mx;
        g_stats[b * 4 + 1] = my;
        g_stats[b * 4 + 2] = mz;
        g_stats[b * 4 + 3] = sm[0] * 2.0f;   // denom (EPS = 0)
    }
}

// ---------------- 2) normalized coords (output) + voxel idx + counts ----------------
__global__ void points_kernel(const float* __restrict__ coords, float* __restrict__ nc_out) {
    int i = blockIdx.x * blockDim.x + threadIdx.x;   // < B*N
    int b = i >> 14;
    int n = i & (Nn - 1);
    float mx = g_stats[b * 4 + 0], my = g_stats[b * 4 + 1];
    float mz = g_stats[b * 4 + 2], dn = g_stats[b * 4 + 3];
    const float* cb = coords + (size_t)b * 3 * Nn;
    float x = cb[n], y = cb[Nn + n], z = cb[2 * Nn + n];

    float ncx = ((x - mx) / dn + 0.5f) * (float)Rr;
    float ncy = ((y - my) / dn + 0.5f) * (float)Rr;
    float ncz = ((z - mz) / dn + 0.5f) * (float)Rr;
    ncx = fminf(fmaxf(ncx, 0.f), (float)(Rr - 1));
    ncy = fminf(fmaxf(ncy, 0.f), (float)(Rr - 1));
    ncz = fminf(fmaxf(ncz, 0.f), (float)(Rr - 1));

    float* nb = nc_out + (size_t)b * 3 * Nn;
    nb[n] = ncx;
    nb[Nn + n] = ncy;
    nb[2 * Nn + n] = ncz;

    int vx = (int)rintf(ncx);   // round-half-even == jnp.round
    int vy = (int)rintf(ncy);
    int vz = (int)rintf(ncz);
    int idx = vx * (Rr * Rr) + vy * Rr + vz;
    g_idx[i] = idx;
    atomicAdd(&g_cnt[b * Vv + idx], 1);
}

// ---------------- 3) compact occupied voxels ----------------
__global__ void compact_kernel() {
    int bv = blockIdx.x * blockDim.x + threadIdx.x;   // < B*V
    int cnt = g_cnt[bv];
    if (cnt > 0) {
        int row = atomicAdd(&g_nrows, 1);
        int off = atomicAdd(&g_cursor, cnt);
        g_vox2row[bv] = row;
        g_row2vox[row] = bv;
        g_rowcnt[row] = cnt;
        g_rowoff[row] = off;
        g_fill[row] = 0;
    }
}

// ---------------- 4) per-point CSR slot ----------------
__global__ void slot_kernel() {
    int i = blockIdx.x * blockDim.x + threadIdx.x;    // < B*N
    int b = i >> 14;
    int bv = b * Vv + g_idx[i];
    int row = g_vox2row[bv];
    int s = atomicAdd(&g_fill[row], 1);
    g_slot[i] = g_rowoff[row] + s;
}

// ---------------- 5) gather-transpose [B][C][N] -> CSR rows [slot][C], float4 both sides ----------------
// tile: 48 channels x 128 points, 256 threads, XOR-swizzled float4 smem cells
__global__ void __launch_bounds__(256) gtrans_kernel(const float* __restrict__ f) {
    __shared__ float4 sm4[48][32];                    // [c][n-quad], cell col swizzled by +c
    __shared__ int s_slot[128];
    int b = blockIdx.z;
    int n0 = blockIdx.x << 7;
    int c0 = blockIdx.y * 48;
    int t = threadIdx.x;

    if (t < 128) s_slot[t] = g_slot[(b << 14) + n0 + t];

    int col4 = t & 31, r0 = t >> 5;                   // 8 rows per iteration
#pragma unroll
    for (int rr = 0; rr < 6; ++rr) {
        int r = r0 + rr * 8;
        float4 v = *reinterpret_cast<const float4*>(
            f + ((size_t)b * Cc + c0 + r) * Nn + n0 + col4 * 4);
        sm4[r][(col4 + r) & 31] = v;                  // conflict-free: distinct cells per lane
    }
    __syncthreads();

    const float* smf = reinterpret_cast<const float*>(sm4);
#pragma unroll
    for (int it = 0; it < 6; ++it) {
        int w = it * 256 + t;                         // < 1536
        int j = w % 12;                               // c-quad within tile
        int p = w / 12;                               // point within tile
        int pq = p >> 2, pk = p & 3;
        float o[4];
#pragma unroll
        for (int kk = 0; kk < 4; ++kk) {
            int r = 4 * j + kk;
            o[kk] = smf[r * 128 + (((pq + r) & 31) << 2) + pk];
        }
        *reinterpret_cast<float4*>(g_featT + (size_t)s_slot[p] * FS + c0 + 4 * j) =
            make_float4(o[0], o[1], o[2], o[3]);
    }
}

// ---------------- 6) reduce: sequential CSR rows, max + avg, float4 ----------------
__global__ void reduce_kernel() {
    int row = blockIdx.x;
    if (row >= g_nrows) return;
    int t = threadIdx.x;                              // 64, use 60
    if (t >= 60) return;
    int cnt = g_rowcnt[row];
    int off = g_rowoff[row];
    const float* base = g_featT + (size_t)off * FS + 4 * t;
    float4 s = make_float4(0.f, 0.f, 0.f, 0.f);
    float4 m = make_float4(-INFINITY, -INFINITY, -INFINITY, -INFINITY);
    for (int p = 0; p < cnt; ++p) {
        float4 v = *reinterpret_cast<const float4*>(base + (size_t)p * FS);
        s.x += v.x; s.y += v.y; s.z += v.z; s.w += v.w;
        m.x = fmaxf(m.x, v.x); m.y = fmaxf(m.y, v.y);
        m.z = fmaxf(m.z, v.z); m.w = fmaxf(m.w, v.w);
    }
    float inv = 1.0f / (float)cnt;
    float* arow = g_A + (size_t)row * K2;
    *reinterpret_cast<float4*>(arow + 4 * t) = m;
    *reinterpret_cast<float4*>(arow + Cc + 4 * t) =
        make_float4(s.x * inv, s.y * inv, s.z * inv, s.w * inv);
}

// ---------------- 7) per-channel empty-voxel constant ----------------
__global__ void empty_kernel(const float* __restrict__ bias,
                             const float* __restrict__ gamma,
                             const float* __restrict__ beta,
                             const float* __restrict__ bmean,
                             const float* __restrict__ bvar) {
    int o = threadIdx.x;
    float s = gamma[o] * rsqrtf(bvar[o] + 1e-5f);
    float y = (bias[o] - bmean[o]) * s + beta[o];
    g_empty[o] = y / (1.0f + expf(-y));
}

// ---------------- 8) fill output with empty constants ----------------
__global__ void fill_out_kernel(float* __restrict__ out) {
    int i = blockIdx.x * blockDim.x + threadIdx.x;    // float4 index < B*C*V/4
    int o = (i >> 13) % Cc;                           // V/4 = 8192 float4 per channel
    float e = g_empty[o];
    reinterpret_cast<float4*>(out)[i] = make_float4(e, e, e, e);
}

// ---------------- 9) tf32 tensor-core GEMM [M=nrows, N=240, K=480] + epilogue ----------------
// BM=128, BN=80, BK=32; 256 threads = 8 warps (4 M x 2 N); warp tile 32x40 (2x5 m16n8k8).
__global__ void __launch_bounds__(256) gemm_kernel(
    const float* __restrict__ W,      // [240][480]
    const float* __restrict__ bias,
    const float* __restrict__ gamma,
    const float* __restrict__ beta,
    const float* __restrict__ bmean,
    const float* __restrict__ bvar,
    float* __restrict__ out)          // [B][240][V]
{
    int nrows = g_nrows;
    int row0 = blockIdx.x << 7;
    if (row0 >= nrows) return;

    __shared__ float As[128][36];     // stride 36: conflict-free frag loads
    __shared__ float Bs[80][36];
    __shared__ float sc_s[80], sc_o[80];

    int tid = threadIdx.x;
    int n0 = blockIdx.y * 80;

    if (tid < 80) {
        int o = n0 + tid;
        float s = gamma[o] * rsqrtf(bvar[o] + 1e-5f);
        sc_s[tid] = s;
        sc_o[tid] = (bias[o] - bmean[o]) * s + beta[o];
    }

    int lane = tid & 31, warp = tid >> 5;
    int wm = warp & 3, wn = warp >> 2;        // warp M/N position
    int grp = lane >> 2, qk = lane & 3;

    float acc[2][5][4];
#pragma unroll
    for (int mt = 0; mt < 2; ++mt)
#pragma unroll
        for (int nt = 0; nt < 5; ++nt)
#pragma unroll
            for (int q = 0; q < 4; ++q) acc[mt][nt][q] = 0.f;

    int am = tid >> 1, ah = (tid & 1) * 16;   // A loader: row am, k-offset ah
    int bn2 = tid >> 1, bh = (tid & 1) * 16;  // B loader (tid < 160)

    for (int kt = 0; kt < 15; ++kt) {
        int kg = kt * 32;
        {   // A tile: 128 rows x 32 k
            const float4* ap = reinterpret_cast<const float4*>(
                g_A + (size_t)(row0 + am) * K2 + kg + ah);
            float4 v0 = ap[0], v1 = ap[1], v2 = ap[2], v3 = ap[3];
            float av[16] = {v0.x, v0.y, v0.z, v0.w, v1.x, v1.y, v1.z, v1.w,
                            v2.x, v2.y, v2.z, v2.w, v3.x, v3.y, v3.z, v3.w};
#pragma unroll
            for (int i = 0; i < 16; ++i) As[am][ah + i] = tf32r(av[i]);
        }
        if (tid < 160) {   // B tile: 80 rows x 32 k
            const float4* bp = reinterpret_cast<const float4*>(
                W + (size_t)(n0 + bn2) * K2 + kg + bh);
            float4 v0 = bp[0], v1 = bp[1], v2 = bp[2], v3 = bp[3];
            float bv[16] = {v0.x, v0.y, v0.z, v0.w, v1.x, v1.y, v1.z, v1.w,
                            v2.x, v2.y, v2.z, v2.w, v3.x, v3.y, v3.z, v3.w};
#pragma unroll
            for (int i = 0; i < 16; ++i) Bs[bn2][bh + i] = tf32r(bv[i]);
        }
        __syncthreads();

#pragma unroll
        for (int ks = 0; ks < 4; ++ks) {
            int k8 = ks * 8;
            uint32_t a[2][4], b[5][2];
#pragma unroll
            for (int mt = 0; mt < 2; ++mt) {
                int r = wm * 32 + mt * 16 + grp;
                a[mt][0] = __float_as_uint(As[r][k8 + qk]);
                a[mt][1] = __float_as_uint(As[r + 8][k8 + qk]);
                a[mt][2] = __float_as_uint(As[r][k8 + qk + 4]);
                a[mt][3] = __float_as_uint(As[r + 8][k8 + qk + 4]);
            }
#pragma unroll
            for (int nt = 0; nt < 5; ++nt) {
                int nc = wn * 40 + nt * 8 + grp;
                b[nt][0] = __float_as_uint(Bs[nc][k8 + qk]);
                b[nt][1] = __float_as_uint(Bs[nc][k8 + qk + 4]);
            }
#pragma unroll
            for (int mt = 0; mt < 2; ++mt)
#pragma unroll
                for (int nt = 0; nt < 5; ++nt)
                    mma_tf32(acc[mt][nt], a[mt], b[nt]);
        }
        __syncthreads();
    }

    // epilogue: y = acc*s + off, swish, scatter to out[b][o][v]
#pragma unroll
    for (int mt = 0; mt < 2; ++mt) {
        int r0 = row0 + wm * 32 + mt * 16 + grp;
        int r1 = r0 + 8;
        int bv0 = (r0 < nrows) ? g_row2vox[r0] : -1;
        int bv1 = (r1 < nrows) ? g_row2vox[r1] : -1;
        size_t ob0 = 0, ob1 = 0;
        if (bv0 >= 0) ob0 = (size_t)(bv0 >> 15) * Cc * Vv + (bv0 & (Vv - 1));
        if (bv1 >= 0) ob1 = (size_t)(bv1 >> 15) * Cc * Vv + (bv1 & (Vv - 1));
#pragma unroll
        for (int nt = 0; nt < 5; ++nt) {
            int ocl = wn * 40 + nt * 8 + 2 * qk;
#pragma unroll
            for (int h = 0; h < 2; ++h) {
                int ol = ocl + h;
                float s = sc_s[ol], off = sc_o[ol];
                int o = n0 + ol;
                if (bv0 >= 0) {
                    float y = acc[mt][nt][h] * s + off;       // c0/c1 -> row r0
                    y = y / (1.0f + expf(-y));
                    out[ob0 + (size_t)o * Vv] = y;
                }
                if (bv1 >= 0) {
                    float y = acc[mt][nt][2 + h] * s + off;   // c2/c3 -> row r1
                    y = y / (1.0f + expf(-y));
                    out[ob1 + (size_t)o * Vv] = y;
                }
            }
        }
    }
}

// ---------------- launch ----------------
extern "C" void kernel_launch(void* const* d_in, const int* in_sizes, int n_in,
                              void* d_out, int out_size) {
    const float* features = (const float*)d_in[0];
    const float* coords   = (const float*)d_in[1];
    const float* conv_w   = (const float*)d_in[2];
    const float* conv_b   = (const float*)d_in[3];
    const float* bn_gamma = (const float*)d_in[4];
    const float* bn_beta  = (const float*)d_in[5];
    const float* bn_mean  = (const float*)d_in[6];
    const float* bn_var   = (const float*)d_in[7];

    float* out = (float*)d_out;                       // [B, C, R^3]
    float* nc_out = out + (size_t)Bn * Cc * Vv;       // [B, 3, N]

    zero_kernel<<<(Bn * Vv) / 256, 256>>>();
    stats_kernel<<<Bn, 512>>>(coords);
    points_kernel<<<(Bn * Nn) / 256, 256>>>(coords, nc_out);
    compact_kernel<<<(Bn * Vv) / 256, 256>>>();
    slot_kernel<<<(Bn * Nn) / 256, 256>>>();
    gtrans_kernel<<<dim3(Nn / 128, 5, Bn), 256>>>(features);
    reduce_kernel<<<MAXROWS, 64>>>();
    empty_kernel<<<1, Cc>>>(conv_b, bn_gamma, bn_beta, bn_mean, bn_var);
    fill_out_kernel<<<(Bn * Cc * Vv) / 4 / 256, 256>>>(out);
    gemm_kernel<<<dim3(MAXROWS / 128, 3), 256>>>(conv_w, conv_b, bn_gamma, bn_beta,
                                                 bn_mean, bn_var, out);
}

// round 5
// speedup vs baseline: 7.7382x; 1.0948x over previous
#include <cuda_runtime.h>
#include <cstdint>
#include <climits>
#include <cmath>

#define Bn 8
#define Cc 240
#define Nn 16384
#define Rr 32
#define Vv 32768              // R^3
#define K2 480                // 2*C
#define FS 256                // padded row stride of g_featT
#define MAXROWS (Bn * Nn)     // worst case (131072)

// ---------------- scratch (static device globals; no allocations) ----------------
__device__ float g_featT[(size_t)Bn * Nn * FS];   // CSR-ordered point features [slot][256]
__device__ float g_A[(size_t)MAXROWS * K2];       // compact GEMM A (tf32-rounded)
__device__ float g_Wt[Cc * K2];                   // tf32-rounded weights
__device__ int   g_cnt[Bn * Vv];
__device__ int   g_idx[Bn * Nn];
__device__ int   g_vox2row[Bn * Vv];
__device__ int   g_row2vox[MAXROWS];
__device__ int   g_rowoff[MAXROWS];
__device__ int   g_rowcnt[MAXROWS];
__device__ int   g_fill[MAXROWS];
__device__ int   g_slot[Bn * Nn];
__device__ unsigned long long g_bsum[1024];       // packed (rows<<32)|points per 256-voxel block
__device__ int   g_nrows;
__device__ float g_stats[Bn * 4];
__device__ float g_empty[Cc];

__device__ __forceinline__ float tf32r(float x) {
    uint32_t u;
    asm("cvt.rna.tf32.f32 %0, %1;" : "=r"(u) : "f"(x));
    return __uint_as_float(u);
}

__device__ __forceinline__ void mma_tf32(float* c, const uint32_t* a, const uint32_t* b) {
    asm volatile(
        "mma.sync.aligned.m16n8k8.row.col.f32.tf32.tf32.f32 "
        "{%0,%1,%2,%3}, {%4,%5,%6,%7}, {%8,%9}, {%0,%1,%2,%3};"
        : "+f"(c[0]), "+f"(c[1]), "+f"(c[2]), "+f"(c[3])
        : "r"(a[0]), "r"(a[1]), "r"(a[2]), "r"(a[3]), "r"(b[0]), "r"(b[1]));
}

__device__ __forceinline__ void cpasync16(void* smem_ptr, const void* gptr) {
    unsigned s = (unsigned)__cvta_generic_to_shared(smem_ptr);
    asm volatile("cp.async.cg.shared.global [%0], [%1], 16;" :: "r"(s), "l"(gptr));
}
__device__ __forceinline__ void cp_commit() { asm volatile("cp.async.commit_group;"); }
template <int N>
__device__ __forceinline__ void cp_wait() { asm volatile("cp.async.wait_group %0;" :: "n"(N)); }

// ---------------- 0) zero voxel counts ----------------
__global__ void zero_kernel() {
    int i = blockIdx.x * blockDim.x + threadIdx.x;   // < B*V
    g_cnt[i] = 0;
}

// ---------------- 1) per-batch mean + max norm ----------------
__global__ void stats_kernel(const float* __restrict__ coords) {
    __shared__ float sm[1024];
    __shared__ float smean[3];
    int b = blockIdx.x, t = threadIdx.x;
    const float* cx = coords + (size_t)b * 3 * Nn;
    float sx = 0.f, sy = 0.f, sz = 0.f;
    for (int n = t; n < Nn; n += 1024) {
        sx += cx[n];
        sy += cx[Nn + n];
        sz += cx[2 * Nn + n];
    }
    float vals[3] = {sx, sy, sz};
    for (int d = 0; d < 3; ++d) {
        sm[t] = vals[d];
        __syncthreads();
        for (int s = 512; s > 0; s >>= 1) {
            if (t < s) sm[t] += sm[t + s];
            __syncthreads();
        }
        if (t == 0) smean[d] = sm[0] / (float)Nn;
        __syncthreads();
    }
    float mx = smean[0], my = smean[1], mz = smean[2];
    float mnorm = 0.f;
    for (int n = t; n < Nn; n += 1024) {
        float x = cx[n] - mx, y = cx[Nn + n] - my, z = cx[2 * Nn + n] - mz;
        mnorm = fmaxf(mnorm, sqrtf(x * x + y * y + z * z));
    }
    sm[t] = mnorm;
    __syncthreads();
    for (int s = 512; s > 0; s >>= 1) {
        if (t < s) sm[t] = fmaxf(sm[t], sm[t + s]);
        __syncthreads();
    }
    if (t == 0) {
        g_stats[b * 4 + 0] = mx;
        g_stats[b * 4 + 1] = my;
        g_stats[b * 4 + 2] = mz;
        g_stats[b * 4 + 3] = sm[0] * 2.0f;   // denom (EPS = 0)
    }
}

// ---------------- 2) normalized coords + voxel idx + counts ----------------
__global__ void points_kernel(const float* __restrict__ coords, float* __restrict__ nc_out) {
    int i = blockIdx.x * blockDim.x + threadIdx.x;   // < B*N
    int b = i >> 14;
    int n = i & (Nn - 1);
    float mx = g_stats[b * 4 + 0], my = g_stats[b * 4 + 1];
    float mz = g_stats[b * 4 + 2], dn = g_stats[b * 4 + 3];
    const float* cb = coords + (size_t)b * 3 * Nn;
    float x = cb[n], y = cb[Nn + n], z = cb[2 * Nn + n];

    float ncx = ((x - mx) / dn + 0.5f) * (float)Rr;
    float ncy = ((y - my) / dn + 0.5f) * (float)Rr;
    float ncz = ((z - mz) / dn + 0.5f) * (float)Rr;
    ncx = fminf(fmaxf(ncx, 0.f), (float)(Rr - 1));
    ncy = fminf(fmaxf(ncy, 0.f), (float)(Rr - 1));
    ncz = fminf(fmaxf(ncz, 0.f), (float)(Rr - 1));

    float* nb = nc_out + (size_t)b * 3 * Nn;
    nb[n] = ncx;
    nb[Nn + n] = ncy;
    nb[2 * Nn + n] = ncz;

    int vx = (int)rintf(ncx);   // round-half-even == jnp.round
    int vy = (int)rintf(ncy);
    int vz = (int)rintf(ncz);
    int idx = vx * (Rr * Rr) + vy * Rr + vz;
    g_idx[i] = idx;
    atomicAdd(&g_cnt[b * Vv + idx], 1);
}

// ---------------- 3a) block totals (256 voxels/block) ----------------
__global__ void scan1_kernel() {
    int blk = blockIdx.x, t = threadIdx.x;
    int cnt = g_cnt[blk * 256 + t];
    unsigned long long v = ((unsigned long long)(cnt > 0) << 32) | (unsigned)cnt;
#pragma unroll
    for (int d = 16; d; d >>= 1) v += __shfl_down_sync(0xffffffffu, v, d);
    __shared__ unsigned long long w[8];
    if ((t & 31) == 0) w[t >> 5] = v;
    __syncthreads();
    if (t == 0) {
        unsigned long long s = 0;
#pragma unroll
        for (int i = 0; i < 8; ++i) s += w[i];
        g_bsum[blk] = s;
    }
}

// ---------------- 3b) exclusive scan of 1024 block sums ----------------
__global__ void scan2_kernel() {
    int t = threadIdx.x, lane = t & 31, w = t >> 5;
    unsigned long long x = g_bsum[t], orig = x;
#pragma unroll
    for (int d = 1; d < 32; d <<= 1) {
        unsigned long long y = __shfl_up_sync(0xffffffffu, x, d);
        if (lane >= d) x += y;
    }
    __shared__ unsigned long long ws[32];
    if (lane == 31) ws[w] = x;
    __syncthreads();
    if (w == 0) {
        unsigned long long y = ws[lane];
#pragma unroll
        for (int d = 1; d < 32; d <<= 1) {
            unsigned long long z = __shfl_up_sync(0xffffffffu, y, d);
            if (lane >= d) y += z;
        }
        ws[lane] = y;
    }
    __syncthreads();
    unsigned long long incl = x + (w ? ws[w - 1] : 0ull);
    g_bsum[t] = incl - orig;                          // exclusive base
    if (t == 1023) g_nrows = (int)(incl >> 32);
}

// ---------------- 3c) assign sorted rows + CSR offsets ----------------
__global__ void scan3_kernel() {
    int blk = blockIdx.x, t = threadIdx.x, lane = t & 31, w = t >> 5;
    int bv = blk * 256 + t;
    int cnt = g_cnt[bv];
    unsigned long long v = ((unsigned long long)(cnt > 0) << 32) | (unsigned)cnt;
    unsigned long long orig = v;
#pragma unroll
    for (int d = 1; d < 32; d <<= 1) {
        unsigned long long y = __shfl_up_sync(0xffffffffu, v, d);
        if (lane >= d) v += y;
    }
    __shared__ unsigned long long ws[8], wexcl[8];
    if (lane == 31) ws[w] = v;
    __syncthreads();
    if (t < 8) {
        unsigned long long s = 0;
        for (int i = 0; i < t; ++i) s += ws[i];
        wexcl[t] = s;
    }
    __syncthreads();
    unsigned long long excl = v - orig + wexcl[w] + g_bsum[blk];
    if (cnt > 0) {
        int row = (int)(excl >> 32);
        int off = (int)(excl & 0xffffffffu);
        g_vox2row[bv] = row;
        g_row2vox[row] = bv;
        g_rowcnt[row] = cnt;
        g_rowoff[row] = off;
        g_fill[row] = 0;
    }
}

// ---------------- 4) per-point CSR slot ----------------
__global__ void slot_kernel() {
    int i = blockIdx.x * blockDim.x + threadIdx.x;    // < B*N
    int b = i >> 14;
    int bv = b * Vv + g_idx[i];
    int row = g_vox2row[bv];
    int s = atomicAdd(&g_fill[row], 1);
    g_slot[i] = g_rowoff[row] + s;
}

// ---------------- 5) gather-transpose [B][C][N] -> CSR rows [slot][C] ----------------
__global__ void __launch_bounds__(256) gtrans_kernel(const float* __restrict__ f) {
    __shared__ float4 sm4[48][32];
    __shared__ int s_slot[128];
    int b = blockIdx.z;
    int n0 = blockIdx.x << 7;
    int c0 = blockIdx.y * 48;
    int t = threadIdx.x;

    if (t < 128) s_slot[t] = g_slot[(b << 14) + n0 + t];

    int col4 = t & 31, r0 = t >> 5;
#pragma unroll
    for (int rr = 0; rr < 6; ++rr) {
        int r = r0 + rr * 8;
        float4 v = *reinterpret_cast<const float4*>(
            f + ((size_t)b * Cc + c0 + r) * Nn + n0 + col4 * 4);
        sm4[r][(col4 + r) & 31] = v;
    }
    __syncthreads();

    const float* smf = reinterpret_cast<const float*>(sm4);
#pragma unroll
    for (int it = 0; it < 6; ++it) {
        int w = it * 256 + t;
        int j = w % 12;
        int p = w / 12;
        int pq = p >> 2, pk = p & 3;
        float o[4];
#pragma unroll
        for (int kk = 0; kk < 4; ++kk) {
            int r = 4 * j + kk;
            o[kk] = smf[r * 128 + (((pq + r) & 31) << 2) + pk];
        }
        *reinterpret_cast<float4*>(g_featT + (size_t)s_slot[p] * FS + c0 + 4 * j) =
            make_float4(o[0], o[1], o[2], o[3]);
    }
}

// ---------------- 6) reduce: sequential CSR rows -> tf32-rounded A ----------------
__global__ void reduce_kernel() {
    int row = blockIdx.x;
    if (row >= g_nrows) return;
    int t = threadIdx.x;
    if (t >= 60) return;
    int cnt = g_rowcnt[row];
    int off = g_rowoff[row];
    const float* base = g_featT + (size_t)off * FS + 4 * t;
    float4 s = make_float4(0.f, 0.f, 0.f, 0.f);
    float4 m = make_float4(-INFINITY, -INFINITY, -INFINITY, -INFINITY);
    for (int p = 0; p < cnt; ++p) {
        float4 v = *reinterpret_cast<const float4*>(base + (size_t)p * FS);
        s.x += v.x; s.y += v.y; s.z += v.z; s.w += v.w;
        m.x = fmaxf(m.x, v.x); m.y = fmaxf(m.y, v.y);
        m.z = fmaxf(m.z, v.z); m.w = fmaxf(m.w, v.w);
    }
    float inv = 1.0f / (float)cnt;
    float* arow = g_A + (size_t)row * K2;
    *reinterpret_cast<float4*>(arow + 4 * t) =
        make_float4(tf32r(m.x), tf32r(m.y), tf32r(m.z), tf32r(m.w));
    *reinterpret_cast<float4*>(arow + Cc + 4 * t) =
        make_float4(tf32r(s.x * inv), tf32r(s.y * inv), tf32r(s.z * inv), tf32r(s.w * inv));
}

// ---------------- 7) per-channel empty-voxel constant ----------------
__global__ void empty_kernel(const float* __restrict__ bias,
                             const float* __restrict__ gamma,
                             const float* __restrict__ beta,
                             const float* __restrict__ bmean,
                             const float* __restrict__ bvar) {
    int o = threadIdx.x;
    float s = gamma[o] * rsqrtf(bvar[o] + 1e-5f);
    float y = (bias[o] - bmean[o]) * s + beta[o];
    g_empty[o] = y / (1.0f + expf(-y));
}

// ---------------- 7b) tf32-round weights ----------------
__global__ void wconv_kernel(const float* __restrict__ W) {
    int i = blockIdx.x * blockDim.x + threadIdx.x;    // < 240*480
    g_Wt[i] = tf32r(W[i]);
}

// ---------------- 8) fill output with empty constants ----------------
__global__ void fill_out_kernel(float* __restrict__ out) {
    int i = blockIdx.x * blockDim.x + threadIdx.x;    // float4 index < B*C*V/4
    int o = (i >> 13) % Cc;
    float e = g_empty[o];
    reinterpret_cast<float4*>(out)[i] = make_float4(e, e, e, e);
}

// ---------------- 9) tf32 GEMM, cp.async double-buffered ----------------
// BM=128, BN=80, BK=32; 256 threads = 8 warps (4Mx2N); warp tile 32x40.
#define AS(s, r, k) As[(((s) * 128 + (r)) * 36) + (k)]
#define BS(s, r, k) Bsm[(((s) * 80 + (r)) * 36) + (k)]
#define GEMM_SMEM ((2 * 128 * 36 + 2 * 80 * 36 + 160) * 4)

__global__ void __launch_bounds__(256) gemm_kernel(
    const float* __restrict__ bias,
    const float* __restrict__ gamma,
    const float* __restrict__ beta,
    const float* __restrict__ bmean,
    const float* __restrict__ bvar,
    float* __restrict__ out)          // [B][240][V]
{
    int nrows = g_nrows;
    int row0 = blockIdx.x << 7;
    if (row0 >= nrows) return;

    extern __shared__ float dsm[];
    float* As  = dsm;                       // [2][128][36]
    float* Bsm = dsm + 2 * 128 * 36;        // [2][80][36]
    float* sc_s = Bsm + 2 * 80 * 36;        // [80]
    float* sc_o = sc_s + 80;

    int tid = threadIdx.x;
    int n0 = blockIdx.y * 80;

    if (tid < 80) {
        int o = n0 + tid;
        float s = gamma[o] * rsqrtf(bvar[o] + 1e-5f);
        sc_s[tid] = s;
        sc_o[tid] = (bias[o] - bmean[o]) * s + beta[o];
    }

    int lane = tid & 31, warp = tid >> 5;
    int wm = warp & 3, wn = warp >> 2;
    int grp = lane >> 2, qk = lane & 3;

    float acc[2][5][4];
#pragma unroll
    for (int mt = 0; mt < 2; ++mt)
#pragma unroll
        for (int nt = 0; nt < 5; ++nt)
#pragma unroll
            for (int q = 0; q < 4; ++q) acc[mt][nt][q] = 0.f;

    int am = tid >> 1, ah = (tid & 1) * 16;   // A loader
    int bn2 = tid >> 1, bh = (tid & 1) * 16;  // B loader (tid < 160)

    auto load_stage = [&](int kt, int s) {
        int kg = kt * 32;
        const float* ap = g_A + (size_t)(row0 + am) * K2 + kg + ah;
#pragma unroll
        for (int i = 0; i < 4; ++i)
            cpasync16(&AS(s, am, ah + 4 * i), ap + 4 * i);
        if (tid < 160) {
            const float* bp = g_Wt + (size_t)(n0 + bn2) * K2 + kg + bh;
#pragma unroll
            for (int i = 0; i < 4; ++i)
                cpasync16(&BS(s, bn2, bh + 4 * i), bp + 4 * i);
        }
        cp_commit();
    };

    load_stage(0, 0);

    for (int kt = 0; kt < 15; ++kt) {
        int s = kt & 1;
        if (kt < 14) {
            load_stage(kt + 1, s ^ 1);
            cp_wait<1>();
        } else {
            cp_wait<0>();
        }
        __syncthreads();

#pragma unroll
        for (int ks = 0; ks < 4; ++ks) {
            int k8 = ks * 8;
            uint32_t a[2][4], b[5][2];
#pragma unroll
            for (int mt = 0; mt < 2; ++mt) {
                int r = wm * 32 + mt * 16 + grp;
                a[mt][0] = __float_as_uint(AS(s, r, k8 + qk));
                a[mt][1] = __float_as_uint(AS(s, r + 8, k8 + qk));
                a[mt][2] = __float_as_uint(AS(s, r, k8 + qk + 4));
                a[mt][3] = __float_as_uint(AS(s, r + 8, k8 + qk + 4));
            }
#pragma unroll
            for (int nt = 0; nt < 5; ++nt) {
                int nc = wn * 40 + nt * 8 + grp;
                b[nt][0] = __float_as_uint(BS(s, nc, k8 + qk));
                b[nt][1] = __float_as_uint(BS(s, nc, k8 + qk + 4));
            }
#pragma unroll
            for (int mt = 0; mt < 2; ++mt)
#pragma unroll
                for (int nt = 0; nt < 5; ++nt)
                    mma_tf32(acc[mt][nt], a[mt], b[nt]);
        }
        __syncthreads();
    }

    // epilogue: BN + swish, scatter to out (rows are voxel-sorted -> coalescing)
#pragma unroll
    for (int mt = 0; mt < 2; ++mt) {
        int r0 = row0 + wm * 32 + mt * 16 + grp;
        int r1 = r0 + 8;
        int bv0 = (r0 < nrows) ? g_row2vox[r0] : -1;
        int bv1 = (r1 < nrows) ? g_row2vox[r1] : -1;
        size_t ob0 = 0, ob1 = 0;
        if (bv0 >= 0) ob0 = (size_t)(bv0 >> 15) * Cc * Vv + (bv0 & (Vv - 1));
        if (bv1 >= 0) ob1 = (size_t)(bv1 >> 15) * Cc * Vv + (bv1 & (Vv - 1));
#pragma unroll
        for (int nt = 0; nt < 5; ++nt) {
            int ocl = wn * 40 + nt * 8 + 2 * qk;
#pragma unroll
            for (int h = 0; h < 2; ++h) {
                int ol = ocl + h;
                float s = sc_s[ol], off = sc_o[ol];
                int o = n0 + ol;
                if (bv0 >= 0) {
                    float y = acc[mt][nt][h] * s + off;
                    y = y / (1.0f + expf(-y));
                    out[ob0 + (size_t)o * Vv] = y;
                }
                if (bv1 >= 0) {
                    float y = acc[mt][nt][2 + h] * s + off;
                    y = y / (1.0f + expf(-y));
                    out[ob1 + (size_t)o * Vv] = y;
                }
            }
        }
    }
}

// ---------------- launch ----------------
extern "C" void kernel_launch(void* const* d_in, const int* in_sizes, int n_in,
                              void* d_out, int out_size) {
    const float* features = (const float*)d_in[0];
    const float* coords   = (const float*)d_in[1];
    const float* conv_w   = (const float*)d_in[2];
    const float* conv_b   = (const float*)d_in[3];
    const float* bn_gamma = (const float*)d_in[4];
    const float* bn_beta  = (const float*)d_in[5];
    const float* bn_mean  = (const float*)d_in[6];
    const float* bn_var   = (const float*)d_in[7];

    float* out = (float*)d_out;                       // [B, C, R^3]
    float* nc_out = out + (size_t)Bn * Cc * Vv;       // [B, 3, N]

    cudaFuncSetAttribute(gemm_kernel, cudaFuncAttributeMaxDynamicSharedMemorySize, GEMM_SMEM);

    zero_kernel<<<(Bn * Vv) / 256, 256>>>();
    stats_kernel<<<Bn, 1024>>>(coords);
    points_kernel<<<(Bn * Nn) / 256, 256>>>(coords, nc_out);
    scan1_kernel<<<1024, 256>>>();
    scan2_kernel<<<1, 1024>>>();
    scan3_kernel<<<1024, 256>>>();
    slot_kernel<<<(Bn * Nn) / 256, 256>>>();
    gtrans_kernel<<<dim3(Nn / 128, 5, Bn), 256>>>(features);
    reduce_kernel<<<MAXROWS, 64>>>();
    empty_kernel<<<1, Cc>>>(conv_b, bn_gamma, bn_beta, bn_mean, bn_var);
    wconv_kernel<<<(Cc * K2) / 256, 256>>>(conv_w);
    fill_out_kernel<<<(Bn * Cc * Vv) / 4 / 256, 256>>>(out);
    gemm_kernel<<<dim3(MAXROWS / 128, 3), 256, GEMM_SMEM>>>(conv_b, bn_gamma, bn_beta,
                                                            bn_mean, bn_var, out);
}

// round 6
// speedup vs baseline: 8.3503x; 1.0791x over previous
#include <cuda_runtime.h>
#include <cstdint>
#include <climits>
#include <cmath>

#define Bn 8
#define Cc 240
#define Nn 16384
#define Rr 32
#define Vv 32768              // R^3
#define K2 480                // 2*C
#define FS 256                // padded row stride of g_featT
#define MAXROWS (Bn * Nn)     // worst case (131072)

// ---------------- scratch (static device globals; no allocations) ----------------
__device__ float g_featT[(size_t)Bn * Nn * FS];   // CSR-ordered point features [slot][256]
__device__ float g_A[(size_t)MAXROWS * K2];       // compact GEMM A (tf32-rounded)
__device__ float g_Y[(size_t)Cc * MAXROWS];       // compact GEMM result, column-major [o][row]
__device__ float g_Wt[Cc * K2];                   // tf32-rounded weights
__device__ int   g_cnt[Bn * Vv];
__device__ int   g_idx[Bn * Nn];
__device__ int   g_vox2row[Bn * Vv];              // -1 if empty
__device__ int   g_rowoff[MAXROWS];
__device__ int   g_rowcnt[MAXROWS];
__device__ int   g_fill[MAXROWS];
__device__ int   g_slot[Bn * Nn];
__device__ unsigned long long g_bsum[1024];       // packed (rows<<32)|points per 256-voxel block
__device__ int   g_nrows;
__device__ float g_stats[Bn * 4];

__device__ __forceinline__ float tf32r(float x) {
    uint32_t u;
    asm("cvt.rna.tf32.f32 %0, %1;" : "=r"(u) : "f"(x));
    return __uint_as_float(u);
}

__device__ __forceinline__ void mma_tf32(float* c, const uint32_t* a, const uint32_t* b) {
    asm volatile(
        "mma.sync.aligned.m16n8k8.row.col.f32.tf32.tf32.f32 "
        "{%0,%1,%2,%3}, {%4,%5,%6,%7}, {%8,%9}, {%0,%1,%2,%3};"
        : "+f"(c[0]), "+f"(c[1]), "+f"(c[2]), "+f"(c[3])
        : "r"(a[0]), "r"(a[1]), "r"(a[2]), "r"(a[3]), "r"(b[0]), "r"(b[1]));
}

__device__ __forceinline__ void cpasync16(void* smem_ptr, const void* gptr) {
    unsigned s = (unsigned)__cvta_generic_to_shared(smem_ptr);
    asm volatile("cp.async.cg.shared.global [%0], [%1], 16;" :: "r"(s), "l"(gptr));
}
__device__ __forceinline__ void cp_commit() { asm volatile("cp.async.commit_group;"); }
template <int N>
__device__ __forceinline__ void cp_wait() { asm volatile("cp.async.wait_group %0;" :: "n"(N)); }

// ---------------- 0) zero voxel counts + empty markers ----------------
__global__ void zero_kernel() {
    int i = blockIdx.x * blockDim.x + threadIdx.x;   // < B*V
    g_cnt[i] = 0;
    g_vox2row[i] = -1;
}

// ---------------- 1) per-batch mean + max norm ----------------
__global__ void stats_kernel(const float* __restrict__ coords) {
    __shared__ float sm[1024];
    __shared__ float smean[3];
    int b = blockIdx.x, t = threadIdx.x;
    const float* cx = coords + (size_t)b * 3 * Nn;
    float sx = 0.f, sy = 0.f, sz = 0.f;
    for (int n = t; n < Nn; n += 1024) {
        sx += cx[n];
        sy += cx[Nn + n];
        sz += cx[2 * Nn + n];
    }
    float vals[3] = {sx, sy, sz};
    for (int d = 0; d < 3; ++d) {
        sm[t] = vals[d];
        __syncthreads();
        for (int s = 512; s > 0; s >>= 1) {
            if (t < s) sm[t] += sm[t + s];
            __syncthreads();
        }
        if (t == 0) smean[d] = sm[0] / (float)Nn;
        __syncthreads();
    }
    float mx = smean[0], my = smean[1], mz = smean[2];
    float mnorm = 0.f;
    for (int n = t; n < Nn; n += 1024) {
        float x = cx[n] - mx, y = cx[Nn + n] - my, z = cx[2 * Nn + n] - mz;
        mnorm = fmaxf(mnorm, sqrtf(x * x + y * y + z * z));
    }
    sm[t] = mnorm;
    __syncthreads();
    for (int s = 512; s > 0; s >>= 1) {
        if (t < s) sm[t] = fmaxf(sm[t], sm[t + s]);
        __syncthreads();
    }
    if (t == 0) {
        g_stats[b * 4 + 0] = mx;
        g_stats[b * 4 + 1] = my;
        g_stats[b * 4 + 2] = mz;
        g_stats[b * 4 + 3] = sm[0] * 2.0f;   // denom (EPS = 0)
    }
}

// ---------------- 2) normalized coords + voxel idx + counts ----------------
__global__ void points_kernel(const float* __restrict__ coords, float* __restrict__ nc_out) {
    int i = blockIdx.x * blockDim.x + threadIdx.x;   // < B*N
    int b = i >> 14;
    int n = i & (Nn - 1);
    float mx = g_stats[b * 4 + 0], my = g_stats[b * 4 + 1];
    float mz = g_stats[b * 4 + 2], dn = g_stats[b * 4 + 3];
    const float* cb = coords + (size_t)b * 3 * Nn;
    float x = cb[n], y = cb[Nn + n], z = cb[2 * Nn + n];

    float ncx = ((x - mx) / dn + 0.5f) * (float)Rr;
    float ncy = ((y - my) / dn + 0.5f) * (float)Rr;
    float ncz = ((z - mz) / dn + 0.5f) * (float)Rr;
    ncx = fminf(fmaxf(ncx, 0.f), (float)(Rr - 1));
    ncy = fminf(fmaxf(ncy, 0.f), (float)(Rr - 1));
    ncz = fminf(fmaxf(ncz, 0.f), (float)(Rr - 1));

    float* nb = nc_out + (size_t)b * 3 * Nn;
    nb[n] = ncx;
    nb[Nn + n] = ncy;
    nb[2 * Nn + n] = ncz;

    int vx = (int)rintf(ncx);   // round-half-even == jnp.round
    int vy = (int)rintf(ncy);
    int vz = (int)rintf(ncz);
    int idx = vx * (Rr * Rr) + vy * Rr + vz;
    g_idx[i] = idx;
    atomicAdd(&g_cnt[b * Vv + idx], 1);
}

// ---------------- 3a) block totals (256 voxels/block) ----------------
__global__ void scan1_kernel() {
    int blk = blockIdx.x, t = threadIdx.x;
    int cnt = g_cnt[blk * 256 + t];
    unsigned long long v = ((unsigned long long)(cnt > 0) << 32) | (unsigned)cnt;
#pragma unroll
    for (int d = 16; d; d >>= 1) v += __shfl_down_sync(0xffffffffu, v, d);
    __shared__ unsigned long long w[8];
    if ((t & 31) == 0) w[t >> 5] = v;
    __syncthreads();
    if (t == 0) {
        unsigned long long s = 0;
#pragma unroll
        for (int i = 0; i < 8; ++i) s += w[i];
        g_bsum[blk] = s;
    }
}

// ---------------- 3b) exclusive scan of 1024 block sums ----------------
__global__ void scan2_kernel() {
    int t = threadIdx.x, lane = t & 31, w = t >> 5;
    unsigned long long x = g_bsum[t], orig = x;
#pragma unroll
    for (int d = 1; d < 32; d <<= 1) {
        unsigned long long y = __shfl_up_sync(0xffffffffu, x, d);
        if (lane >= d) x += y;
    }
    __shared__ unsigned long long ws[32];
    if (lane == 31) ws[w] = x;
    __syncthreads();
    if (w == 0) {
        unsigned long long y = ws[lane];
#pragma unroll
        for (int d = 1; d < 32; d <<= 1) {
            unsigned long long z = __shfl_up_sync(0xffffffffu, y, d);
            if (lane >= d) y += z;
        }
        ws[lane] = y;
    }
    __syncthreads();
    unsigned long long incl = x + (w ? ws[w - 1] : 0ull);
    g_bsum[t] = incl - orig;                          // exclusive base
    if (t == 1023) g_nrows = (int)(incl >> 32);
}

// ---------------- 3c) assign sorted rows + CSR offsets ----------------
__global__ void scan3_kernel() {
    int blk = blockIdx.x, t = threadIdx.x, lane = t & 31, w = t >> 5;
    int bv = blk * 256 + t;
    int cnt = g_cnt[bv];
    unsigned long long v = ((unsigned long long)(cnt > 0) << 32) | (unsigned)cnt;
    unsigned long long orig = v;
#pragma unroll
    for (int d = 1; d < 32; d <<= 1) {
        unsigned long long y = __shfl_up_sync(0xffffffffu, v, d);
        if (lane >= d) v += y;
    }
    __shared__ unsigned long long ws[8], wexcl[8];
    if (lane == 31) ws[w] = v;
    __syncthreads();
    if (t < 8) {
        unsigned long long s = 0;
        for (int i = 0; i < t; ++i) s += ws[i];
        wexcl[t] = s;
    }
    __syncthreads();
    unsigned long long excl = v - orig + wexcl[w] + g_bsum[blk];
    if (cnt > 0) {
        int row = (int)(excl >> 32);
        int off = (int)(excl & 0xffffffffu);
        g_vox2row[bv] = row;
        g_rowcnt[row] = cnt;
        g_rowoff[row] = off;
        g_fill[row] = 0;
    }
}

// ---------------- 4) per-point CSR slot ----------------
__global__ void slot_kernel() {
    int i = blockIdx.x * blockDim.x + threadIdx.x;    // < B*N
    int b = i >> 14;
    int bv = b * Vv + g_idx[i];
    int row = g_vox2row[bv];
    int s = atomicAdd(&g_fill[row], 1);
    g_slot[i] = g_rowoff[row] + s;
}

// ---------------- 5) gather-transpose [B][C][N] -> CSR rows [slot][C] ----------------
__global__ void __launch_bounds__(256) gtrans_kernel(const float* __restrict__ f) {
    __shared__ float4 sm4[48][32];
    __shared__ int s_slot[128];
    int b = blockIdx.z;
    int n0 = blockIdx.x << 7;
    int c0 = blockIdx.y * 48;
    int t = threadIdx.x;

    if (t < 128) s_slot[t] = g_slot[(b << 14) + n0 + t];

    int col4 = t & 31, r0 = t >> 5;
#pragma unroll
    for (int rr = 0; rr < 6; ++rr) {
        int r = r0 + rr * 8;
        float4 v = *reinterpret_cast<const float4*>(
            f + ((size_t)b * Cc + c0 + r) * Nn + n0 + col4 * 4);
        sm4[r][(col4 + r) & 31] = v;
    }
    __syncthreads();

    const float* smf = reinterpret_cast<const float*>(sm4);
#pragma unroll
    for (int it = 0; it < 6; ++it) {
        int w = it * 256 + t;
        int j = w % 12;
        int p = w / 12;
        int pq = p >> 2, pk = p & 3;
        float o[4];
#pragma unroll
        for (int kk = 0; kk < 4; ++kk) {
            int r = 4 * j + kk;
            o[kk] = smf[r * 128 + (((pq + r) & 31) << 2) + pk];
        }
        *reinterpret_cast<float4*>(g_featT + (size_t)s_slot[p] * FS + c0 + 4 * j) =
            make_float4(o[0], o[1], o[2], o[3]);
    }
}

// ---------------- 6) reduce: persistent grid, CSR rows -> tf32-rounded A ----------------
__global__ void reduce_kernel() {
    int nrows = g_nrows;
    int t = threadIdx.x;
    if (t >= 60) return;
    for (int row = blockIdx.x; row < nrows; row += gridDim.x) {
        int cnt = g_rowcnt[row];
        int off = g_rowoff[row];
        const float* base = g_featT + (size_t)off * FS + 4 * t;
        float4 s = make_float4(0.f, 0.f, 0.f, 0.f);
        float4 m = make_float4(-INFINITY, -INFINITY, -INFINITY, -INFINITY);
        for (int p = 0; p < cnt; ++p) {
            float4 v = *reinterpret_cast<const float4*>(base + (size_t)p * FS);
            s.x += v.x; s.y += v.y; s.z += v.z; s.w += v.w;
            m.x = fmaxf(m.x, v.x); m.y = fmaxf(m.y, v.y);
            m.z = fmaxf(m.z, v.z); m.w = fmaxf(m.w, v.w);
        }
        float inv = 1.0f / (float)cnt;
        float* arow = g_A + (size_t)row * K2;
        *reinterpret_cast<float4*>(arow + 4 * t) =
            make_float4(tf32r(m.x), tf32r(m.y), tf32r(m.z), tf32r(m.w));
        *reinterpret_cast<float4*>(arow + Cc + 4 * t) =
            make_float4(tf32r(s.x * inv), tf32r(s.y * inv), tf32r(s.z * inv), tf32r(s.w * inv));
    }
}

// ---------------- 7) tf32-round weights ----------------
__global__ void wconv_kernel(const float* __restrict__ W) {
    int i = blockIdx.x * blockDim.x + threadIdx.x;    // < 240*480
    g_Wt[i] = tf32r(W[i]);
}

// ---------------- 8) tf32 GEMM -> compact g_Y[o][row], cp.async double-buffered ----------------
// BM=128, BN=80, BK=32; 256 threads = 8 warps (4Mx2N); warp tile 32x40.
#define AS(s, r, k) As[(((s) * 128 + (r)) * 36) + (k)]
#define BS(s, r, k) Bsm[(((s) * 80 + (r)) * 36) + (k)]
#define GEMM_SMEM ((2 * 128 * 36 + 2 * 80 * 36 + 160) * 4)

__global__ void __launch_bounds__(256) gemm_kernel(
    const float* __restrict__ bias,
    const float* __restrict__ gamma,
    const float* __restrict__ beta,
    const float* __restrict__ bmean,
    const float* __restrict__ bvar)
{
    int nrows = g_nrows;
    int row0 = blockIdx.x << 7;
    if (row0 >= nrows) return;

    extern __shared__ float dsm[];
    float* As  = dsm;                       // [2][128][36]
    float* Bsm = dsm + 2 * 128 * 36;        // [2][80][36]
    float* sc_s = Bsm + 2 * 80 * 36;        // [80]
    float* sc_o = sc_s + 80;

    int tid = threadIdx.x;
    int n0 = blockIdx.y * 80;

    if (tid < 80) {
        int o = n0 + tid;
        float s = gamma[o] * rsqrtf(bvar[o] + 1e-5f);
        sc_s[tid] = s;
        sc_o[tid] = (bias[o] - bmean[o]) * s + beta[o];
    }

    int lane = tid & 31, warp = tid >> 5;
    int wm = warp & 3, wn = warp >> 2;
    int grp = lane >> 2, qk = lane & 3;

    float acc[2][5][4];
#pragma unroll
    for (int mt = 0; mt < 2; ++mt)
#pragma unroll
        for (int nt = 0; nt < 5; ++nt)
#pragma unroll
            for (int q = 0; q < 4; ++q) acc[mt][nt][q] = 0.f;

    int am = tid >> 1, ah = (tid & 1) * 16;   // A loader
    int bn2 = tid >> 1, bh = (tid & 1) * 16;  // B loader (tid < 160)

    auto load_stage = [&](int kt, int s) {
        int kg = kt * 32;
        const float* ap = g_A + (size_t)(row0 + am) * K2 + kg + ah;
#pragma unroll
        for (int i = 0; i < 4; ++i)
            cpasync16(&AS(s, am, ah + 4 * i), ap + 4 * i);
        if (tid < 160) {
            const float* bp = g_Wt + (size_t)(n0 + bn2) * K2 + kg + bh;
#pragma unroll
            for (int i = 0; i < 4; ++i)
                cpasync16(&BS(s, bn2, bh + 4 * i), bp + 4 * i);
        }
        cp_commit();
    };

    load_stage(0, 0);

    for (int kt = 0; kt < 15; ++kt) {
        int s = kt & 1;
        if (kt < 14) {
            load_stage(kt + 1, s ^ 1);
            cp_wait<1>();
        } else {
            cp_wait<0>();
        }
        __syncthreads();

#pragma unroll
        for (int ks = 0; ks < 4; ++ks) {
            int k8 = ks * 8;
            uint32_t a[2][4], b[5][2];
#pragma unroll
            for (int mt = 0; mt < 2; ++mt) {
                int r = wm * 32 + mt * 16 + grp;
                a[mt][0] = __float_as_uint(AS(s, r, k8 + qk));
                a[mt][1] = __float_as_uint(AS(s, r + 8, k8 + qk));
                a[mt][2] = __float_as_uint(AS(s, r, k8 + qk + 4));
                a[mt][3] = __float_as_uint(AS(s, r + 8, k8 + qk + 4));
            }
#pragma unroll
            for (int nt = 0; nt < 5; ++nt) {
                int nc = wn * 40 + nt * 8 + grp;
                b[nt][0] = __float_as_uint(BS(s, nc, k8 + qk));
                b[nt][1] = __float_as_uint(BS(s, nc, k8 + qk + 4));
            }
#pragma unroll
            for (int mt = 0; mt < 2; ++mt)
#pragma unroll
                for (int nt = 0; nt < 5; ++nt)
                    mma_tf32(acc[mt][nt], a[mt], b[nt]);
        }
        __syncthreads();
    }

    // epilogue: BN + swish -> compact g_Y[o][row] (coalesced: 8 grp-lanes = 8 consecutive rows)
#pragma unroll
    for (int mt = 0; mt < 2; ++mt) {
        int r0 = row0 + wm * 32 + mt * 16 + grp;
        int r1 = r0 + 8;
        bool v0 = r0 < nrows, v1 = r1 < nrows;
#pragma unroll
        for (int nt = 0; nt < 5; ++nt) {
            int ocl = wn * 40 + nt * 8 + 2 * qk;
#pragma unroll
            for (int h = 0; h < 2; ++h) {
                int ol = ocl + h;
                float s = sc_s[ol], off = sc_o[ol];
                size_t ocol = (size_t)(n0 + ol) * MAXROWS;
                if (v0) {
                    float y = acc[mt][nt][h] * s + off;
                    g_Y[ocol + r0] = y / (1.0f + expf(-y));
                }
                if (v1) {
                    float y = acc[mt][nt][2 + h] * s + off;
                    g_Y[ocol + r1] = y / (1.0f + expf(-y));
                }
            }
        }
    }
}

// ---------------- 9) final output: fully coalesced merge of g_Y + empty constants ----------------
// grid (B*V/1024, 4); block 256. Each block: 1024-voxel span, 60 channels.
__global__ void __launch_bounds__(256) write_out_kernel(
    const float* __restrict__ bias,
    const float* __restrict__ gamma,
    const float* __restrict__ beta,
    const float* __restrict__ bmean,
    const float* __restrict__ bvar,
    float* __restrict__ out)          // [B][240][V]
{
    __shared__ float s_empty[60];
    int t = threadIdx.x;
    int span = blockIdx.x;            // < B*V/1024
    int o0 = blockIdx.y * 60;
    int b = span >> 5;                // V/1024 = 32 spans per batch
    int v0 = (span & 31) << 10;

    if (t < 60) {
        int o = o0 + t;
        float s = gamma[o] * rsqrtf(bvar[o] + 1e-5f);
        float y = (bias[o] - bmean[o]) * s + beta[o];
        s_empty[t] = y / (1.0f + expf(-y));
    }
    // 4 voxels per thread, kept in registers across the channel loop
    int4 rows = *reinterpret_cast<const int4*>(g_vox2row + b * Vv + v0 + 4 * t);
    __syncthreads();

    size_t obase = (size_t)b * Cc * Vv + v0 + 4 * t;
    for (int j = 0; j < 60; ++j) {
        int o = o0 + j;
        float e = s_empty[j];
        const float* ycol = g_Y + (size_t)o * MAXROWS;
        float4 r;
        r.x = (rows.x >= 0) ? ycol[rows.x] : e;
        r.y = (rows.y >= 0) ? ycol[rows.y] : e;
        r.z = (rows.z >= 0) ? ycol[rows.z] : e;
        r.w = (rows.w >= 0) ? ycol[rows.w] : e;
        *reinterpret_cast<float4*>(out + obase + (size_t)o * Vv) = r;
    }
}

// ---------------- launch ----------------
extern "C" void kernel_launch(void* const* d_in, const int* in_sizes, int n_in,
                              void* d_out, int out_size) {
    const float* features = (const float*)d_in[0];
    const float* coords   = (const float*)d_in[1];
    const float* conv_w   = (const float*)d_in[2];
    const float* conv_b   = (const float*)d_in[3];
    const float* bn_gamma = (const float*)d_in[4];
    const float* bn_beta  = (const float*)d_in[5];
    const float* bn_mean  = (const float*)d_in[6];
    const float* bn_var   = (const float*)d_in[7];

    float* out = (float*)d_out;                       // [B, C, R^3]
    float* nc_out = out + (size_t)Bn * Cc * Vv;       // [B, 3, N]

    cudaFuncSetAttribute(gemm_kernel, cudaFuncAttributeMaxDynamicSharedMemorySize, GEMM_SMEM);

    zero_kernel<<<(Bn * Vv) / 256, 256>>>();
    stats_kernel<<<Bn, 1024>>>(coords);
    points_kernel<<<(Bn * Nn) / 256, 256>>>(coords, nc_out);
    scan1_kernel<<<1024, 256>>>();
    scan2_kernel<<<1, 1024>>>();
    scan3_kernel<<<1024, 256>>>();
    slot_kernel<<<(Bn * Nn) / 256, 256>>>();
    gtrans_kernel<<<dim3(Nn / 128, 5, Bn), 256>>>(features);
    reduce_kernel<<<2048, 64>>>();
    wconv_kernel<<<(Cc * K2) / 256, 256>>>(conv_w);
    gemm_kernel<<<dim3(MAXROWS / 128, 3), 256, GEMM_SMEM>>>(conv_b, bn_gamma, bn_beta,
                                                            bn_mean, bn_var);
    write_out_kernel<<<dim3((Bn * Vv) / 1024, 4), 256>>>(conv_b, bn_gamma, bn_beta,
                                                         bn_mean, bn_var, out);
}

// round 7
// speedup vs baseline: 8.5955x; 1.0294x over previous
#include <cuda_runtime.h>
#include <cstdint>
#include <climits>
#include <cmath>

#define Bn 8
#define Cc 240
#define Nn 16384
#define Rr 32
#define Vv 32768              // R^3
#define K2 480                // 2*C
#define FS 256                // padded row stride of g_featT
#define MAXROWS (Bn * Nn)     // worst case (131072)

// ---------------- scratch (static device globals; no allocations) ----------------
__device__ float g_featT[(size_t)Bn * Nn * FS];   // CSR-ordered point features [slot][256]
__device__ float g_A[(size_t)MAXROWS * K2];       // compact GEMM A (tf32-rounded)
__device__ float g_Y[(size_t)Cc * MAXROWS];       // compact GEMM result, column-major [o][row]
__device__ float g_Wt[Cc * K2];                   // tf32-rounded weights
__device__ int   g_cnt[Bn * Vv];
__device__ int   g_idx[Bn * Nn];
__device__ int   g_vox2row[Bn * Vv];              // -1 if empty
__device__ int   g_rowoff[MAXROWS];
__device__ int   g_rowcnt[MAXROWS];
__device__ int   g_fill[MAXROWS];
__device__ int   g_slot[Bn * Nn];
__device__ unsigned long long g_bsum[1024];       // packed (rows<<32)|points per 256-voxel block
__device__ int   g_nrows;
__device__ float g_stats[Bn * 4];

__device__ __forceinline__ float tf32r(float x) {
    uint32_t u;
    asm("cvt.rna.tf32.f32 %0, %1;" : "=r"(u) : "f"(x));
    return __uint_as_float(u);
}

__device__ __forceinline__ void mma_tf32(float* c, const uint32_t* a, const uint32_t* b) {
    asm volatile(
        "mma.sync.aligned.m16n8k8.row.col.f32.tf32.tf32.f32 "
        "{%0,%1,%2,%3}, {%4,%5,%6,%7}, {%8,%9}, {%0,%1,%2,%3};"
        : "+f"(c[0]), "+f"(c[1]), "+f"(c[2]), "+f"(c[3])
        : "r"(a[0]), "r"(a[1]), "r"(a[2]), "r"(a[3]), "r"(b[0]), "r"(b[1]));
}

__device__ __forceinline__ void cpasync16(void* smem_ptr, const void* gptr) {
    unsigned s = (unsigned)__cvta_generic_to_shared(smem_ptr);
    asm volatile("cp.async.cg.shared.global [%0], [%1], 16;" :: "r"(s), "l"(gptr));
}
__device__ __forceinline__ void cp_commit() { asm volatile("cp.async.commit_group;"); }
template <int N>
__device__ __forceinline__ void cp_wait() { asm volatile("cp.async.wait_group %0;" :: "n"(N)); }

// ---------------- 0) zero voxel counts + empty markers + tf32-round W ----------------
__global__ void zero_kernel(const float* __restrict__ W) {
    int i = blockIdx.x * blockDim.x + threadIdx.x;   // < B*V
    g_cnt[i] = 0;
    g_vox2row[i] = -1;
    if (i < Cc * K2) g_Wt[i] = tf32r(W[i]);
}

// ---------------- 1) per-batch mean + max norm ----------------
__global__ void stats_kernel(const float* __restrict__ coords) {
    __shared__ float sm[1024];
    __shared__ float smean[3];
    int b = blockIdx.x, t = threadIdx.x;
    const float* cx = coords + (size_t)b * 3 * Nn;
    float sx = 0.f, sy = 0.f, sz = 0.f;
    for (int n = t; n < Nn; n += 1024) {
        sx += cx[n];
        sy += cx[Nn + n];
        sz += cx[2 * Nn + n];
    }
    float vals[3] = {sx, sy, sz};
    for (int d = 0; d < 3; ++d) {
        sm[t] = vals[d];
        __syncthreads();
        for (int s = 512; s > 0; s >>= 1) {
            if (t < s) sm[t] += sm[t + s];
            __syncthreads();
        }
        if (t == 0) smean[d] = sm[0] / (float)Nn;
        __syncthreads();
    }
    float mx = smean[0], my = smean[1], mz = smean[2];
    float mnorm = 0.f;
    for (int n = t; n < Nn; n += 1024) {
        float x = cx[n] - mx, y = cx[Nn + n] - my, z = cx[2 * Nn + n] - mz;
        mnorm = fmaxf(mnorm, sqrtf(x * x + y * y + z * z));
    }
    sm[t] = mnorm;
    __syncthreads();
    for (int s = 512; s > 0; s >>= 1) {
        if (t < s) sm[t] = fmaxf(sm[t], sm[t + s]);
        __syncthreads();
    }
    if (t == 0) {
        g_stats[b * 4 + 0] = mx;
        g_stats[b * 4 + 1] = my;
        g_stats[b * 4 + 2] = mz;
        g_stats[b * 4 + 3] = sm[0] * 2.0f;   // denom (EPS = 0)
    }
}

// ---------------- 2) normalized coords + voxel idx + counts ----------------
__global__ void points_kernel(const float* __restrict__ coords, float* __restrict__ nc_out) {
    int i = blockIdx.x * blockDim.x + threadIdx.x;   // < B*N
    int b = i >> 14;
    int n = i & (Nn - 1);
    float mx = g_stats[b * 4 + 0], my = g_stats[b * 4 + 1];
    float mz = g_stats[b * 4 + 2], dn = g_stats[b * 4 + 3];
    const float* cb = coords + (size_t)b * 3 * Nn;
    float x = cb[n], y = cb[Nn + n], z = cb[2 * Nn + n];

    float ncx = ((x - mx) / dn + 0.5f) * (float)Rr;
    float ncy = ((y - my) / dn + 0.5f) * (float)Rr;
    float ncz = ((z - mz) / dn + 0.5f) * (float)Rr;
    ncx = fminf(fmaxf(ncx, 0.f), (float)(Rr - 1));
    ncy = fminf(fmaxf(ncy, 0.f), (float)(Rr - 1));
    ncz = fminf(fmaxf(ncz, 0.f), (float)(Rr - 1));

    float* nb = nc_out + (size_t)b * 3 * Nn;
    nb[n] = ncx;
    nb[Nn + n] = ncy;
    nb[2 * Nn + n] = ncz;

    int vx = (int)rintf(ncx);   // round-half-even == jnp.round
    int vy = (int)rintf(ncy);
    int vz = (int)rintf(ncz);
    int idx = vx * (Rr * Rr) + vy * Rr + vz;
    g_idx[i] = idx;
    atomicAdd(&g_cnt[b * Vv + idx], 1);
}

// ---------------- 3a) block totals (256 voxels/block) ----------------
__global__ void scan1_kernel() {
    int blk = blockIdx.x, t = threadIdx.x;
    int cnt = g_cnt[blk * 256 + t];
    unsigned long long v = ((unsigned long long)(cnt > 0) << 32) | (unsigned)cnt;
#pragma unroll
    for (int d = 16; d; d >>= 1) v += __shfl_down_sync(0xffffffffu, v, d);
    __shared__ unsigned long long w[8];
    if ((t & 31) == 0) w[t >> 5] = v;
    __syncthreads();
    if (t == 0) {
        unsigned long long s = 0;
#pragma unroll
        for (int i = 0; i < 8; ++i) s += w[i];
        g_bsum[blk] = s;
    }
}

// ---------------- 3b) exclusive scan of 1024 block sums ----------------
__global__ void scan2_kernel() {
    int t = threadIdx.x, lane = t & 31, w = t >> 5;
    unsigned long long x = g_bsum[t], orig = x;
#pragma unroll
    for (int d = 1; d < 32; d <<= 1) {
        unsigned long long y = __shfl_up_sync(0xffffffffu, x, d);
        if (lane >= d) x += y;
    }
    __shared__ unsigned long long ws[32];
    if (lane == 31) ws[w] = x;
    __syncthreads();
    if (w == 0) {
        unsigned long long y = ws[lane];
#pragma unroll
        for (int d = 1; d < 32; d <<= 1) {
            unsigned long long z = __shfl_up_sync(0xffffffffu, y, d);
            if (lane >= d) y += z;
        }
        ws[lane] = y;
    }
    __syncthreads();
    unsigned long long incl = x + (w ? ws[w - 1] : 0ull);
    g_bsum[t] = incl - orig;                          // exclusive base
    if (t == 1023) g_nrows = (int)(incl >> 32);
}

// ---------------- 3c) assign sorted rows + CSR offsets ----------------
__global__ void scan3_kernel() {
    int blk = blockIdx.x, t = threadIdx.x, lane = t & 31, w = t >> 5;
    int bv = blk * 256 + t;
    int cnt = g_cnt[bv];
    unsigned long long v = ((unsigned long long)(cnt > 0) << 32) | (unsigned)cnt;
    unsigned long long orig = v;
#pragma unroll
    for (int d = 1; d < 32; d <<= 1) {
        unsigned long long y = __shfl_up_sync(0xffffffffu, v, d);
        if (lane >= d) v += y;
    }
    __shared__ unsigned long long ws[8], wexcl[8];
    if (lane == 31) ws[w] = v;
    __syncthreads();
    if (t < 8) {
        unsigned long long s = 0;
        for (int i = 0; i < t; ++i) s += ws[i];
        wexcl[t] = s;
    }
    __syncthreads();
    unsigned long long excl = v - orig + wexcl[w] + g_bsum[blk];
    if (cnt > 0) {
        int row = (int)(excl >> 32);
        int off = (int)(excl & 0xffffffffu);
        g_vox2row[bv] = row;
        g_rowcnt[row] = cnt;
        g_rowoff[row] = off;
        g_fill[row] = 0;
    }
}

// ---------------- 4) per-point CSR slot ----------------
__global__ void slot_kernel() {
    int i = blockIdx.x * blockDim.x + threadIdx.x;    // < B*N
    int b = i >> 14;
    int bv = b * Vv + g_idx[i];
    int row = g_vox2row[bv];
    int s = atomicAdd(&g_fill[row], 1);
    g_slot[i] = g_rowoff[row] + s;
}

// ---------------- 5) gather-transpose [B][C][N] -> CSR rows [slot][C] ----------------
__global__ void __launch_bounds__(256) gtrans_kernel(const float* __restrict__ f) {
    __shared__ float4 sm4[48][32];
    __shared__ int s_slot[128];
    int b = blockIdx.z;
    int n0 = blockIdx.x << 7;
    int c0 = blockIdx.y * 48;
    int t = threadIdx.x;

    if (t < 128) s_slot[t] = g_slot[(b << 14) + n0 + t];

    int col4 = t & 31, r0 = t >> 5;
#pragma unroll
    for (int rr = 0; rr < 6; ++rr) {
        int r = r0 + rr * 8;
        float4 v = *reinterpret_cast<const float4*>(
            f + ((size_t)b * Cc + c0 + r) * Nn + n0 + col4 * 4);
        sm4[r][(col4 + r) & 31] = v;
    }
    __syncthreads();

    const float* smf = reinterpret_cast<const float*>(sm4);
#pragma unroll
    for (int it = 0; it < 6; ++it) {
        int w = it * 256 + t;
        int j = w % 12;
        int p = w / 12;
        int pq = p >> 2, pk = p & 3;
        float o[4];
#pragma unroll
        for (int kk = 0; kk < 4; ++kk) {
            int r = 4 * j + kk;
            o[kk] = smf[r * 128 + (((pq + r) & 31) << 2) + pk];
        }
        *reinterpret_cast<float4*>(g_featT + (size_t)s_slot[p] * FS + c0 + 4 * j) =
            make_float4(o[0], o[1], o[2], o[3]);
    }
}

// ---------------- 6) reduce: persistent grid, CSR rows -> tf32-rounded A ----------------
__global__ void reduce_kernel() {
    int nrows = g_nrows;
    int t = threadIdx.x;
    if (t >= 60) return;
    for (int row = blockIdx.x; row < nrows; row += gridDim.x) {
        int cnt = g_rowcnt[row];
        int off = g_rowoff[row];
        const float* base = g_featT + (size_t)off * FS + 4 * t;
        float4 s = make_float4(0.f, 0.f, 0.f, 0.f);
        float4 m = make_float4(-INFINITY, -INFINITY, -INFINITY, -INFINITY);
        for (int p = 0; p < cnt; ++p) {
            float4 v = *reinterpret_cast<const float4*>(base + (size_t)p * FS);
            s.x += v.x; s.y += v.y; s.z += v.z; s.w += v.w;
            m.x = fmaxf(m.x, v.x); m.y = fmaxf(m.y, v.y);
            m.z = fmaxf(m.z, v.z); m.w = fmaxf(m.w, v.w);
        }
        float inv = 1.0f / (float)cnt;
        float* arow = g_A + (size_t)row * K2;
        *reinterpret_cast<float4*>(arow + 4 * t) =
            make_float4(tf32r(m.x), tf32r(m.y), tf32r(m.z), tf32r(m.w));
        *reinterpret_cast<float4*>(arow + Cc + 4 * t) =
            make_float4(tf32r(s.x * inv), tf32r(s.y * inv), tf32r(s.z * inv), tf32r(s.w * inv));
    }
}

// ---------------- 7) tf32 GEMM single-pass N=240 -> compact g_Y[o][row] ----------------
// BM=128, BN=240, BK=32; 384 threads = 12 warps (4M x 3N); warp tile 32x80 (2x10 m16n8k8).
#define AS(s, r, k) As[(((s) * 128 + (r)) * 36) + (k)]
#define BS(s, r, k) Bsm[(((s) * 240 + (r)) * 36) + (k)]
#define GEMM_SMEM ((2 * 128 * 36 + 2 * 240 * 36 + 2 * 240) * 4)

__global__ void __launch_bounds__(384) gemm_kernel(
    const float* __restrict__ bias,
    const float* __restrict__ gamma,
    const float* __restrict__ beta,
    const float* __restrict__ bmean,
    const float* __restrict__ bvar)
{
    int nrows = g_nrows;
    int row0 = blockIdx.x << 7;
    if (row0 >= nrows) return;

    extern __shared__ float dsm[];
    float* As  = dsm;                       // [2][128][36]
    float* Bsm = dsm + 2 * 128 * 36;        // [2][240][36]
    float* sc_s = Bsm + 2 * 240 * 36;       // [240]
    float* sc_o = sc_s + 240;

    int tid = threadIdx.x;

    if (tid < 240) {
        float s = gamma[tid] * rsqrtf(bvar[tid] + 1e-5f);
        sc_s[tid] = s;
        sc_o[tid] = (bias[tid] - bmean[tid]) * s + beta[tid];
    }

    int lane = tid & 31, warp = tid >> 5;
    int wm = warp & 3, wn = warp >> 2;        // 4 M-warps x 3 N-warps
    int grp = lane >> 2, qk = lane & 3;

    float acc[2][10][4];
#pragma unroll
    for (int mt = 0; mt < 2; ++mt)
#pragma unroll
        for (int nt = 0; nt < 10; ++nt)
#pragma unroll
            for (int q = 0; q < 4; ++q) acc[mt][nt][q] = 0.f;

    int am = tid >> 1, ah = (tid & 1) * 16;   // A loader (tid < 256)

    auto load_stage = [&](int kt, int s) {
        int kg = kt * 32;
        if (tid < 256) {
            const float* ap = g_A + (size_t)(row0 + am) * K2 + kg + ah;
#pragma unroll
            for (int i = 0; i < 4; ++i)
                cpasync16(&AS(s, am, ah + 4 * i), ap + 4 * i);
        }
        // B tile: 240 rows x 32 k = 1920 float4; 384 threads x 5
#pragma unroll
        for (int i = 0; i < 5; ++i) {
            int idx = tid + 384 * i;              // < 1920
            int rowb = idx >> 3;                  // 8 float4 per row
            int c4 = (idx & 7) << 2;
            cpasync16(&BS(s, rowb, c4), g_Wt + (size_t)rowb * K2 + kg + c4);
        }
        cp_commit();
    };

    load_stage(0, 0);

    for (int kt = 0; kt < 15; ++kt) {
        int s = kt & 1;
        if (kt < 14) {
            load_stage(kt + 1, s ^ 1);
            cp_wait<1>();
        } else {
            cp_wait<0>();
        }
        __syncthreads();

#pragma unroll
        for (int ks = 0; ks < 4; ++ks) {
            int k8 = ks * 8;
            uint32_t a[2][4], b[10][2];
#pragma unroll
            for (int mt = 0; mt < 2; ++mt) {
                int r = wm * 32 + mt * 16 + grp;
                a[mt][0] = __float_as_uint(AS(s, r, k8 + qk));
                a[mt][1] = __float_as_uint(AS(s, r + 8, k8 + qk));
                a[mt][2] = __float_as_uint(AS(s, r, k8 + qk + 4));
                a[mt][3] = __float_as_uint(AS(s, r + 8, k8 + qk + 4));
            }
#pragma unroll
            for (int nt = 0; nt < 10; ++nt) {
                int nc = wn * 80 + nt * 8 + grp;
                b[nt][0] = __float_as_uint(BS(s, nc, k8 + qk));
                b[nt][1] = __float_as_uint(BS(s, nc, k8 + qk + 4));
            }
#pragma unroll
            for (int mt = 0; mt < 2; ++mt)
#pragma unroll
                for (int nt = 0; nt < 10; ++nt)
                    mma_tf32(acc[mt][nt], a[mt], b[nt]);
        }
        __syncthreads();
    }

    // epilogue: BN + swish -> compact g_Y[o][row]
#pragma unroll
    for (int mt = 0; mt < 2; ++mt) {
        int r0 = row0 + wm * 32 + mt * 16 + grp;
        int r1 = r0 + 8;
        bool v0 = r0 < nrows, v1 = r1 < nrows;
#pragma unroll
        for (int nt = 0; nt < 10; ++nt) {
            int ocl = wn * 80 + nt * 8 + 2 * qk;
#pragma unroll
            for (int h = 0; h < 2; ++h) {
                int o = ocl + h;
                float s = sc_s[o], off = sc_o[o];
                size_t ocol = (size_t)o * MAXROWS;
                if (v0) {
                    float y = acc[mt][nt][h] * s + off;
                    g_Y[ocol + r0] = y / (1.0f + expf(-y));
                }
                if (v1) {
                    float y = acc[mt][nt][2 + h] * s + off;
                    g_Y[ocol + r1] = y / (1.0f + expf(-y));
                }
            }
        }
    }
}

// ---------------- 8) final output: fully coalesced merge of g_Y + empty constants ----------------
// grid (B*V/1024, 4); block 256. Each block: 1024-voxel span, 60 channels.
__global__ void __launch_bounds__(256) write_out_kernel(
    const float* __restrict__ bias,
    const float* __restrict__ gamma,
    const float* __restrict__ beta,
    const float* __restrict__ bmean,
    const float* __restrict__ bvar,
    float* __restrict__ out)          // [B][240][V]
{
    __shared__ float s_empty[60];
    int t = threadIdx.x;
    int span = blockIdx.x;            // < B*V/1024
    int o0 = blockIdx.y * 60;
    int b = span >> 5;                // V/1024 = 32 spans per batch
    int v0 = (span & 31) << 10;

    if (t < 60) {
        int o = o0 + t;
        float s = gamma[o] * rsqrtf(bvar[o] + 1e-5f);
        float y = (bias[o] - bmean[o]) * s + beta[o];
        s_empty[t] = y / (1.0f + expf(-y));
    }
    int4 rows = *reinterpret_cast<const int4*>(g_vox2row + b * Vv + v0 + 4 * t);
    __syncthreads();

    size_t obase = (size_t)b * Cc * Vv + v0 + 4 * t;
    for (int j = 0; j < 60; ++j) {
        int o = o0 + j;
        float e = s_empty[j];
        const float* ycol = g_Y + (size_t)o * MAXROWS;
        float4 r;
        r.x = (rows.x >= 0) ? ycol[rows.x] : e;
        r.y = (rows.y >= 0) ? ycol[rows.y] : e;
        r.z = (rows.z >= 0) ? ycol[rows.z] : e;
        r.w = (rows.w >= 0) ? ycol[rows.w] : e;
        *reinterpret_cast<float4*>(out + obase + (size_t)o * Vv) = r;
    }
}

// ---------------- launch ----------------
extern "C" void kernel_launch(void* const* d_in, const int* in_sizes, int n_in,
                              void* d_out, int out_size) {
    const float* features = (const float*)d_in[0];
    const float* coords   = (const float*)d_in[1];
    const float* conv_w   = (const float*)d_in[2];
    const float* conv_b   = (const float*)d_in[3];
    const float* bn_gamma = (const float*)d_in[4];
    const float* bn_beta  = (const float*)d_in[5];
    const float* bn_mean  = (const float*)d_in[6];
    const float* bn_var   = (const float*)d_in[7];

    float* out = (float*)d_out;                       // [B, C, R^3]
    float* nc_out = out + (size_t)Bn * Cc * Vv;       // [B, 3, N]

    cudaFuncSetAttribute(gemm_kernel, cudaFuncAttributeMaxDynamicSharedMemorySize, GEMM_SMEM);

    zero_kernel<<<(Bn * Vv) / 256, 256>>>(conv_w);
    stats_kernel<<<Bn, 1024>>>(coords);
    points_kernel<<<(Bn * Nn) / 256, 256>>>(coords, nc_out);
    scan1_kernel<<<1024, 256>>>();
    scan2_kernel<<<1, 1024>>>();
    scan3_kernel<<<1024, 256>>>();
    slot_kernel<<<(Bn * Nn) / 256, 256>>>();
    gtrans_kernel<<<dim3(Nn / 128, 5, Bn), 256>>>(features);
    reduce_kernel<<<2048, 64>>>();
    gemm_kernel<<<MAXROWS / 128, 384, GEMM_SMEM>>>(conv_b, bn_gamma, bn_beta,
                                                   bn_mean, bn_var);
    write_out_kernel<<<dim3((Bn * Vv) / 1024, 4), 256>>>(conv_b, bn_gamma, bn_beta,
                                                         bn_mean, bn_var, out);
}

// round 8
// speedup vs baseline: 9.5137x; 1.1068x over previous
#include <cuda_runtime.h>
#include <cstdint>
#include <climits>
#include <cmath>

#define Bn 8
#define Cc 240
#define Nn 16384
#define Rr 32
#define Vv 32768              // R^3
#define K2 480                // 2*C
#define FS 256                // padded row stride of g_featT
#define MAXROWS (Bn * Nn)     // worst case (131072)

// ---------------- scratch (static device globals; no allocations) ----------------
__device__ float g_featT[(size_t)Bn * Nn * FS];   // CSR-ordered point features [slot][256]
__device__ float g_A[(size_t)MAXROWS * K2];       // compact GEMM A (tf32-rounded)
__device__ float g_Y[(size_t)Cc * MAXROWS];       // compact GEMM result, column-major [o][row]
__device__ float g_Wt[Cc * K2];                   // tf32-rounded weights
__device__ int   g_cnt[Bn * Vv];
__device__ int   g_idx[Bn * Nn];
__device__ int   g_vox2row[Bn * Vv];              // -1 if empty
__device__ int   g_rowoff[MAXROWS];
__device__ int   g_rowcnt[MAXROWS];
__device__ int   g_fill[MAXROWS];
__device__ int   g_slot[Bn * Nn];
__device__ unsigned long long g_bsum[1024];       // packed (rows<<32)|points per 256-voxel block
__device__ int   g_nrows;
__device__ float g_stats[Bn * 4];

__device__ __forceinline__ float tf32r(float x) {
    uint32_t u;
    asm("cvt.rna.tf32.f32 %0, %1;" : "=r"(u) : "f"(x));
    return __uint_as_float(u);
}

__device__ __forceinline__ void mma_tf32(float* c, const uint32_t* a, const uint32_t* b) {
    asm volatile(
        "mma.sync.aligned.m16n8k8.row.col.f32.tf32.tf32.f32 "
        "{%0,%1,%2,%3}, {%4,%5,%6,%7}, {%8,%9}, {%0,%1,%2,%3};"
        : "+f"(c[0]), "+f"(c[1]), "+f"(c[2]), "+f"(c[3])
        : "r"(a[0]), "r"(a[1]), "r"(a[2]), "r"(a[3]), "r"(b[0]), "r"(b[1]));
}

__device__ __forceinline__ void cpasync16(void* smem_ptr, const void* gptr) {
    unsigned s = (unsigned)__cvta_generic_to_shared(smem_ptr);
    asm volatile("cp.async.cg.shared.global [%0], [%1], 16;" :: "r"(s), "l"(gptr));
}
__device__ __forceinline__ void cp_commit() { asm volatile("cp.async.commit_group;"); }
template <int N>
__device__ __forceinline__ void cp_wait() { asm volatile("cp.async.wait_group %0;" :: "n"(N)); }

// ---------------- 0) zero voxel counts + empty markers + tf32-round W ----------------
__global__ void zero_kernel(const float* __restrict__ W) {
    int i = blockIdx.x * blockDim.x + threadIdx.x;   // < B*V
    g_cnt[i] = 0;
    g_vox2row[i] = -1;
    if (i < Cc * K2) g_Wt[i] = tf32r(W[i]);
}

// ---------------- 1) per-batch mean + max norm ----------------
__global__ void stats_kernel(const float* __restrict__ coords) {
    __shared__ float sm[1024];
    __shared__ float smean[3];
    int b = blockIdx.x, t = threadIdx.x;
    const float* cx = coords + (size_t)b * 3 * Nn;
    float sx = 0.f, sy = 0.f, sz = 0.f;
    for (int n = t; n < Nn; n += 1024) {
        sx += cx[n];
        sy += cx[Nn + n];
        sz += cx[2 * Nn + n];
    }
    float vals[3] = {sx, sy, sz};
    for (int d = 0; d < 3; ++d) {
        sm[t] = vals[d];
        __syncthreads();
        for (int s = 512; s > 0; s >>= 1) {
            if (t < s) sm[t] += sm[t + s];
            __syncthreads();
        }
        if (t == 0) smean[d] = sm[0] / (float)Nn;
        __syncthreads();
    }
    float mx = smean[0], my = smean[1], mz = smean[2];
    float mnorm = 0.f;
    for (int n = t; n < Nn; n += 1024) {
        float x = cx[n] - mx, y = cx[Nn + n] - my, z = cx[2 * Nn + n] - mz;
        mnorm = fmaxf(mnorm, sqrtf(x * x + y * y + z * z));
    }
    sm[t] = mnorm;
    __syncthreads();
    for (int s = 512; s > 0; s >>= 1) {
        if (t < s) sm[t] = fmaxf(sm[t], sm[t + s]);
        __syncthreads();
    }
    if (t == 0) {
        g_stats[b * 4 + 0] = mx;
        g_stats[b * 4 + 1] = my;
        g_stats[b * 4 + 2] = mz;
        g_stats[b * 4 + 3] = sm[0] * 2.0f;   // denom (EPS = 0)
    }
}

// ---------------- 2) normalized coords + voxel idx + counts ----------------
__global__ void points_kernel(const float* __restrict__ coords, float* __restrict__ nc_out) {
    int i = blockIdx.x * blockDim.x + threadIdx.x;   // < B*N
    int b = i >> 14;
    int n = i & (Nn - 1);
    float mx = g_stats[b * 4 + 0], my = g_stats[b * 4 + 1];
    float mz = g_stats[b * 4 + 2], dn = g_stats[b * 4 + 3];
    const float* cb = coords + (size_t)b * 3 * Nn;
    float x = cb[n], y = cb[Nn + n], z = cb[2 * Nn + n];

    float ncx = ((x - mx) / dn + 0.5f) * (float)Rr;
    float ncy = ((y - my) / dn + 0.5f) * (float)Rr;
    float ncz = ((z - mz) / dn + 0.5f) * (float)Rr;
    ncx = fminf(fmaxf(ncx, 0.f), (float)(Rr - 1));
    ncy = fminf(fmaxf(ncy, 0.f), (float)(Rr - 1));
    ncz = fminf(fmaxf(ncz, 0.f), (float)(Rr - 1));

    float* nb = nc_out + (size_t)b * 3 * Nn;
    nb[n] = ncx;
    nb[Nn + n] = ncy;
    nb[2 * Nn + n] = ncz;

    int vx = (int)rintf(ncx);   // round-half-even == jnp.round
    int vy = (int)rintf(ncy);
    int vz = (int)rintf(ncz);
    int idx = vx * (Rr * Rr) + vy * Rr + vz;
    g_idx[i] = idx;
    atomicAdd(&g_cnt[b * Vv + idx], 1);
}

// ---------------- 3a) block totals (256 voxels/block) ----------------
__global__ void scan1_kernel() {
    int blk = blockIdx.x, t = threadIdx.x;
    int cnt = g_cnt[blk * 256 + t];
    unsigned long long v = ((unsigned long long)(cnt > 0) << 32) | (unsigned)cnt;
#pragma unroll
    for (int d = 16; d; d >>= 1) v += __shfl_down_sync(0xffffffffu, v, d);
    __shared__ unsigned long long w[8];
    if ((t & 31) == 0) w[t >> 5] = v;
    __syncthreads();
    if (t == 0) {
        unsigned long long s = 0;
#pragma unroll
        for (int i = 0; i < 8; ++i) s += w[i];
        g_bsum[blk] = s;
    }
}

// ---------------- 3b) rows+offsets: every block redundantly scans the 1024 bsums ----------------
__global__ void scan3_kernel() {
    int blk = blockIdx.x, t = threadIdx.x, lane = t & 31, w = t >> 5;

    // --- redundant exclusive scan of g_bsum[0..1023] to get this block's base ---
    __shared__ unsigned long long part[256];
    {
        const unsigned long long* bs = g_bsum + 4 * t;
        unsigned long long s4 = bs[0] + bs[1] + bs[2] + bs[3];
        part[t] = s4;
    }
    __syncthreads();
    // exclusive prefix over part[0..blk>>2 - 1] + partial within chunk
    // block-wide scan of part via warp scans
    unsigned long long x = part[t];
#pragma unroll
    for (int d = 1; d < 32; d <<= 1) {
        unsigned long long y = __shfl_up_sync(0xffffffffu, x, d);
        if (lane >= d) x += y;
    }
    __shared__ unsigned long long wsum[8];
    if (lane == 31) wsum[w] = x;
    __syncthreads();
    __shared__ unsigned long long wexc[8];
    if (t < 8) {
        unsigned long long s = 0;
        for (int i = 0; i < t; ++i) s += wsum[i];
        wexc[t] = s;
    }
    __syncthreads();
    __shared__ unsigned long long s_base, s_total;
    if (t == (blk >> 2)) {
        unsigned long long excl_chunk = x - part[t] + wexc[w];   // exclusive over chunks < blk/4
        const unsigned long long* bs = g_bsum + (blk & ~3);
        for (int i = 0; i < (blk & 3); ++i) excl_chunk += bs[i];
        s_base = excl_chunk;
    }
    if (t == 255) s_total = x + wexc[7];
    __syncthreads();
    if (blk == 0 && t == 0) g_nrows = (int)(s_total >> 32);

    // --- local scan over this block's 256 voxels ---
    int bv = blk * 256 + t;
    int cnt = g_cnt[bv];
    unsigned long long v = ((unsigned long long)(cnt > 0) << 32) | (unsigned)cnt;
    unsigned long long orig = v;
#pragma unroll
    for (int d = 1; d < 32; d <<= 1) {
        unsigned long long y = __shfl_up_sync(0xffffffffu, v, d);
        if (lane >= d) v += y;
    }
    __syncthreads();
    if (lane == 31) wsum[w] = v;
    __syncthreads();
    if (t < 8) {
        unsigned long long s = 0;
        for (int i = 0; i < t; ++i) s += wsum[i];
        wexc[t] = s;
    }
    __syncthreads();
    unsigned long long excl = v - orig + wexc[w] + s_base;
    if (cnt > 0) {
        int row = (int)(excl >> 32);
        int off = (int)(excl & 0xffffffffu);
        g_vox2row[bv] = row;
        g_rowcnt[row] = cnt;
        g_rowoff[row] = off;
        g_fill[row] = 0;
    }
}

// ---------------- 4) per-point CSR slot ----------------
__global__ void slot_kernel() {
    int i = blockIdx.x * blockDim.x + threadIdx.x;    // < B*N
    int b = i >> 14;
    int bv = b * Vv + g_idx[i];
    int row = g_vox2row[bv];
    int s = atomicAdd(&g_fill[row], 1);
    g_slot[i] = g_rowoff[row] + s;
}

// ---------------- 5) gather-transpose [B][C][N] -> CSR rows [slot][C] ----------------
__global__ void __launch_bounds__(256) gtrans_kernel(const float* __restrict__ f) {
    __shared__ float4 sm4[48][32];
    __shared__ int s_slot[128];
    int b = blockIdx.z;
    int n0 = blockIdx.x << 7;
    int c0 = blockIdx.y * 48;
    int t = threadIdx.x;

    if (t < 128) s_slot[t] = g_slot[(b << 14) + n0 + t];

    int col4 = t & 31, r0 = t >> 5;
#pragma unroll
    for (int rr = 0; rr < 6; ++rr) {
        int r = r0 + rr * 8;
        float4 v = *reinterpret_cast<const float4*>(
            f + ((size_t)b * Cc + c0 + r) * Nn + n0 + col4 * 4);
        sm4[r][(col4 + r) & 31] = v;
    }
    __syncthreads();

    const float* smf = reinterpret_cast<const float*>(sm4);
#pragma unroll
    for (int it = 0; it < 6; ++it) {
        int w = it * 256 + t;
        int j = w % 12;
        int p = w / 12;
        int pq = p >> 2, pk = p & 3;
        float o[4];
#pragma unroll
        for (int kk = 0; kk < 4; ++kk) {
            int r = 4 * j + kk;
            o[kk] = smf[r * 128 + (((pq + r) & 31) << 2) + pk];
        }
        *reinterpret_cast<float4*>(g_featT + (size_t)s_slot[p] * FS + c0 + 4 * j) =
            make_float4(o[0], o[1], o[2], o[3]);
    }
}

// ---------------- 6) reduce: 4 row-groups per block, CSR rows -> tf32-rounded A ----------------
__global__ void __launch_bounds__(256) reduce_kernel() {
    int nrows = g_nrows;
    int t = threadIdx.x & 63;            // lane within group
    int grpi = threadIdx.x >> 6;         // 0..3
    if (t >= 60) return;
    for (int row = blockIdx.x * 4 + grpi; row < nrows; row += gridDim.x * 4) {
        int cnt = g_rowcnt[row];
        int off = g_rowoff[row];
        const float4* base = reinterpret_cast<const float4*>(
            g_featT + (size_t)off * FS + 4 * t);
        float4 s = make_float4(0.f, 0.f, 0.f, 0.f);
        float4 m = make_float4(-INFINITY, -INFINITY, -INFINITY, -INFINITY);
        for (int p = 0; p < cnt; ++p) {
            float4 v = __ldcs(base + (size_t)p * (FS / 4));
            s.x += v.x; s.y += v.y; s.z += v.z; s.w += v.w;
            m.x = fmaxf(m.x, v.x); m.y = fmaxf(m.y, v.y);
            m.z = fmaxf(m.z, v.z); m.w = fmaxf(m.w, v.w);
        }
        float inv = 1.0f / (float)cnt;
        float* arow = g_A + (size_t)row * K2;
        *reinterpret_cast<float4*>(arow + 4 * t) =
            make_float4(tf32r(m.x), tf32r(m.y), tf32r(m.z), tf32r(m.w));
        *reinterpret_cast<float4*>(arow + Cc + 4 * t) =
            make_float4(tf32r(s.x * inv), tf32r(s.y * inv), tf32r(s.z * inv), tf32r(s.w * inv));
    }
}

// ---------------- 7) tf32 GEMM single-pass N=240, persistent grid -> g_Y[o][row] ----------------
// BM=128, BN=240, BK=32; 384 threads = 12 warps (4M x 3N); warp tile 32x80.
#define AS(s, r, k) As[(((s) * 128 + (r)) * 36) + (k)]
#define BS(s, r, k) Bsm[(((s) * 240 + (r)) * 36) + (k)]
#define GEMM_SMEM ((2 * 128 * 36 + 2 * 240 * 36 + 2 * 240) * 4)
#define GEMM_GRID 296

__global__ void __launch_bounds__(384) gemm_kernel(
    const float* __restrict__ bias,
    const float* __restrict__ gamma,
    const float* __restrict__ beta,
    const float* __restrict__ bmean,
    const float* __restrict__ bvar)
{
    int nrows = g_nrows;
    int ntiles = (nrows + 127) >> 7;

    extern __shared__ float dsm[];
    float* As  = dsm;                       // [2][128][36]
    float* Bsm = dsm + 2 * 128 * 36;        // [2][240][36]
    float* sc_s = Bsm + 2 * 240 * 36;       // [240]
    float* sc_o = sc_s + 240;

    int tid = threadIdx.x;

    if (tid < 240) {
        float s = gamma[tid] * rsqrtf(bvar[tid] + 1e-5f);
        sc_s[tid] = s;
        sc_o[tid] = (bias[tid] - bmean[tid]) * s + beta[tid];
    }

    int lane = tid & 31, warp = tid >> 5;
    int wm = warp & 3, wn = warp >> 2;        // 4 M-warps x 3 N-warps
    int grp = lane >> 2, qk = lane & 3;
    int am = tid >> 1, ah = (tid & 1) * 16;   // A loader (tid < 256)

    for (int tile = blockIdx.x; tile < ntiles; tile += GEMM_GRID) {
        int row0 = tile << 7;

        float acc[2][10][4];
#pragma unroll
        for (int mt = 0; mt < 2; ++mt)
#pragma unroll
            for (int nt = 0; nt < 10; ++nt)
#pragma unroll
                for (int q = 0; q < 4; ++q) acc[mt][nt][q] = 0.f;

        auto load_stage = [&](int kt, int s) {
            int kg = kt * 32;
            if (tid < 256) {
                const float* ap = g_A + (size_t)(row0 + am) * K2 + kg + ah;
#pragma unroll
                for (int i = 0; i < 4; ++i)
                    cpasync16(&AS(s, am, ah + 4 * i), ap + 4 * i);
            }
#pragma unroll
            for (int i = 0; i < 5; ++i) {
                int idx = tid + 384 * i;              // < 1920
                int rowb = idx >> 3;
                int c4 = (idx & 7) << 2;
                cpasync16(&BS(s, rowb, c4), g_Wt + (size_t)rowb * K2 + kg + c4);
            }
            cp_commit();
        };

        __syncthreads();      // protect smem reuse across tiles
        load_stage(0, 0);

        for (int kt = 0; kt < 15; ++kt) {
            int s = kt & 1;
            if (kt < 14) {
                load_stage(kt + 1, s ^ 1);
                cp_wait<1>();
            } else {
                cp_wait<0>();
            }
            __syncthreads();

#pragma unroll
            for (int ks = 0; ks < 4; ++ks) {
                int k8 = ks * 8;
                uint32_t a[2][4], b[10][2];
#pragma unroll
                for (int mt = 0; mt < 2; ++mt) {
                    int r = wm * 32 + mt * 16 + grp;
                    a[mt][0] = __float_as_uint(AS(s, r, k8 + qk));
                    a[mt][1] = __float_as_uint(AS(s, r + 8, k8 + qk));
                    a[mt][2] = __float_as_uint(AS(s, r, k8 + qk + 4));
                    a[mt][3] = __float_as_uint(AS(s, r + 8, k8 + qk + 4));
                }
#pragma unroll
                for (int nt = 0; nt < 10; ++nt) {
                    int nc = wn * 80 + nt * 8 + grp;
                    b[nt][0] = __float_as_uint(BS(s, nc, k8 + qk));
                    b[nt][1] = __float_as_uint(BS(s, nc, k8 + qk + 4));
                }
#pragma unroll
                for (int mt = 0; mt < 2; ++mt)
#pragma unroll
                    for (int nt = 0; nt < 10; ++nt)
                        mma_tf32(acc[mt][nt], a[mt], b[nt]);
            }
            __syncthreads();
        }

        // epilogue: BN + swish -> compact g_Y[o][row]
#pragma unroll
        for (int mt = 0; mt < 2; ++mt) {
            int r0 = row0 + wm * 32 + mt * 16 + grp;
            int r1 = r0 + 8;
            bool v0 = r0 < nrows, v1 = r1 < nrows;
#pragma unroll
            for (int nt = 0; nt < 10; ++nt) {
                int ocl = wn * 80 + nt * 8 + 2 * qk;
#pragma unroll
                for (int h = 0; h < 2; ++h) {
                    int o = ocl + h;
                    float s = sc_s[o], off = sc_o[o];
                    size_t ocol = (size_t)o * MAXROWS;
                    if (v0) {
                        float y = acc[mt][nt][h] * s + off;
                        g_Y[ocol + r0] = y / (1.0f + expf(-y));
                    }
                    if (v1) {
                        float y = acc[mt][nt][2 + h] * s + off;
                        g_Y[ocol + r1] = y / (1.0f + expf(-y));
                    }
                }
            }
        }
    }
}

// ---------------- 8) final output: coalesced merge of g_Y + empty constants ----------------
__global__ void __launch_bounds__(256) write_out_kernel(
    const float* __restrict__ bias,
    const float* __restrict__ gamma,
    const float* __restrict__ beta,
    const float* __restrict__ bmean,
    const float* __restrict__ bvar,
    float* __restrict__ out)          // [B][240][V]
{
    __shared__ float s_empty[60];
    int t = threadIdx.x;
    int span = blockIdx.x;            // < B*V/1024
    int o0 = blockIdx.y * 60;
    int b = span >> 5;                // 32 spans per batch
    int v0 = (span & 31) << 10;

    if (t < 60) {
        int o = o0 + t;
        float s = gamma[o] * rsqrtf(bvar[o] + 1e-5f);
        float y = (bias[o] - bmean[o]) * s + beta[o];
        s_empty[t] = y / (1.0f + expf(-y));
    }
    int4 rows = *reinterpret_cast<const int4*>(g_vox2row + b * Vv + v0 + 4 * t);
    __syncthreads();

    size_t obase = (size_t)b * Cc * Vv + v0 + 4 * t;
    for (int j = 0; j < 60; ++j) {
        int o = o0 + j;
        float e = s_empty[j];
        const float* ycol = g_Y + (size_t)o * MAXROWS;
        float4 r;
        r.x = (rows.x >= 0) ? ycol[rows.x] : e;
        r.y = (rows.y >= 0) ? ycol[rows.y] : e;
        r.z = (rows.z >= 0) ? ycol[rows.z] : e;
        r.w = (rows.w >= 0) ? ycol[rows.w] : e;
        __stcs(reinterpret_cast<float4*>(out + obase + (size_t)o * Vv), r);
    }
}

// ---------------- launch ----------------
extern "C" void kernel_launch(void* const* d_in, const int* in_sizes, int n_in,
                              void* d_out, int out_size) {
    const float* features = (const float*)d_in[0];
    const float* coords   = (const float*)d_in[1];
    const float* conv_w   = (const float*)d_in[2];
    const float* conv_b   = (const float*)d_in[3];
    const float* bn_gamma = (const float*)d_in[4];
    const float* bn_beta  = (const float*)d_in[5];
    const float* bn_mean  = (const float*)d_in[6];
    const float* bn_var   = (const float*)d_in[7];

    float* out = (float*)d_out;                       // [B, C, R^3]
    float* nc_out = out + (size_t)Bn * Cc * Vv;       // [B, 3, N]

    cudaFuncSetAttribute(gemm_kernel, cudaFuncAttributeMaxDynamicSharedMemorySize, GEMM_SMEM);

    zero_kernel<<<(Bn * Vv) / 256, 256>>>(conv_w);
    stats_kernel<<<Bn, 1024>>>(coords);
    points_kernel<<<(Bn * Nn) / 256, 256>>>(coords, nc_out);
    scan1_kernel<<<1024, 256>>>();
    scan3_kernel<<<1024, 256>>>();
    slot_kernel<<<(Bn * Nn) / 256, 256>>>();
    gtrans_kernel<<<dim3(Nn / 128, 5, Bn), 256>>>(features);
    reduce_kernel<<<1024, 256>>>();
    gemm_kernel<<<GEMM_GRID, 384, GEMM_SMEM>>>(conv_b, bn_gamma, bn_beta,
                                               bn_mean, bn_var);
    write_out_kernel<<<dim3((Bn * Vv) / 1024, 4), 256>>>(conv_b, bn_gamma, bn_beta,
                                                         bn_mean, bn_var, out);
}